// round 13
// baseline (speedup 1.0000x reference)
#include <cuda_runtime.h>
#include <cuda_bf16.h>
#include <float.h>
#include <math.h>
#include <stdint.h>

// Problem constants
#define NB 8
#define NN 256
#define NM 512
#define NE 1024
#define NH 32
#define ND 32
#define NEXT 768   // N + M

#define SCALING_F 0.17677669529663687f  // 32^-0.5

// ---------------- device scratch ----------------
static __device__ float g_attn[(long long)NB*NH*NN*NEXT];   // probs (fp32)
static __device__ float g_delta[(long long)NB*NN*3*NEXT];   // masked delta [b,n,c,m]
static __device__ __nv_bfloat16 g_ah[8192LL*1024];
static __device__ __nv_bfloat16 g_al[8192LL*1024];
static __device__ __nv_bfloat16 g_wh[6LL*1024*1024];
static __device__ __nv_bfloat16 g_wl[6LL*1024*1024];
static __device__ __nv_bfloat16 g_projh[4LL*2048*1024];
static __device__ __nv_bfloat16 g_projl[4LL*2048*1024];
#define PSZ 2097152
#define VOFF 2097152

// ============================================================================
// helpers
// ============================================================================
__device__ __forceinline__ uint32_t smem_u32(const void* p) {
    uint32_t a;
    asm("{ .reg .u64 t; cvta.to.shared.u64 t, %1; cvt.u32.u64 %0, t; }"
        : "=r"(a) : "l"(p));
    return a;
}
#define CP_ASYNC16(sa, ga) \
    asm volatile("cp.async.cg.shared.global [%0], [%1], 16;\n" :: "r"(sa), "l"(ga))
#define CP_COMMIT() asm volatile("cp.async.commit_group;\n" ::: "memory")
#define CP_WAIT(n)  asm volatile("cp.async.wait_group %0;\n" :: "n"(n) : "memory")

__device__ __forceinline__ void mma16816(float* c, const uint32_t* a, const uint32_t* b) {
    asm volatile(
        "mma.sync.aligned.m16n8k16.row.col.f32.bf16.bf16.f32 "
        "{%0,%1,%2,%3}, {%4,%5,%6,%7}, {%8,%9}, {%0,%1,%2,%3};\n"
        : "+f"(c[0]), "+f"(c[1]), "+f"(c[2]), "+f"(c[3])
        : "r"(a[0]), "r"(a[1]), "r"(a[2]), "r"(a[3]), "r"(b[0]), "r"(b[1]));
}
__device__ __forceinline__ void ldsm4(uint32_t& r0, uint32_t& r1, uint32_t& r2,
                                      uint32_t& r3, uint32_t a) {
    asm volatile("ldmatrix.sync.aligned.m8n8.x4.shared.b16 {%0,%1,%2,%3}, [%4];"
                 : "=r"(r0), "=r"(r1), "=r"(r2), "=r"(r3) : "r"(a));
}
// fast split (bit-identical rn rounding)
__device__ __forceinline__ void split2(float a, float b, uint32_t& hi, uint32_t& lo) {
    asm("cvt.rn.bf16x2.f32 %0, %1, %2;" : "=r"(hi) : "f"(b), "f"(a));
    float ha = __uint_as_float(hi << 16);
    float hb = __uint_as_float(hi & 0xffff0000u);
    asm("cvt.rn.bf16x2.f32 %0, %1, %2;" : "=r"(lo) : "f"(b - hb), "f"(a - ha));
}
__device__ __forceinline__ float sqrt_approx(float x) {
    float r;
    asm("sqrt.approx.f32 %0, %1;" : "=f"(r) : "f"(x));
    return r;
}
__device__ __forceinline__ float rcp_approx(float x) {
    float r;
    asm("rcp.approx.f32 %0, %1;" : "=f"(r) : "f"(x));
    return r;
}

// ============================================================================
// converters
// ============================================================================
__global__ __launch_bounds__(256) void cvt_split_x(const float* __restrict__ src,
                                                   __nv_bfloat16* __restrict__ hi,
                                                   __nv_bfloat16* __restrict__ lo)
{
    int i = blockIdx.x * 256 + threadIdx.x;
    int r  = i >> 8;
    int e4 = (i & 255) << 2;
    int b = r >> 8, n = r & 255;
    float4 v = *(const float4*)(src + ((long long)n * NB + b) * NE + e4);
    uint32_t h0, l0, h1, l1;
    split2(v.x, v.y, h0, l0);
    split2(v.z, v.w, h1, l1);
    ((uint2*)hi)[i] = make_uint2(h0, h1);
    ((uint2*)lo)[i] = make_uint2(l0, l1);
}

__global__ __launch_bounds__(256) void cvt_split_w(const float* __restrict__ W0,
                                                   const float* __restrict__ W1,
                                                   const float* __restrict__ W2,
                                                   const float* __restrict__ W3,
                                                   const float* __restrict__ W4,
                                                   const float* __restrict__ W5,
                                                   __nv_bfloat16* __restrict__ hi,
                                                   __nv_bfloat16* __restrict__ lo)
{
    int w = blockIdx.y;
    const float* src = (w == 0) ? W0 : (w == 1) ? W1 : (w == 2) ? W2
                     : (w == 3) ? W3 : (w == 4) ? W4 : W5;
    int i = blockIdx.x * 256 + threadIdx.x;
    float4 v = ((const float4*)src)[i];
    uint32_t h0, l0, h1, l1;
    split2(v.x, v.y, h0, l0);
    split2(v.z, v.w, h1, l1);
    size_t o = ((size_t)w << 18) + i;
    ((uint2*)hi)[o] = make_uint2(h0, h1);
    ((uint2*)lo)[o] = make_uint2(l0, l1);
}

// ============================================================================
// Precompute masked delta [b,n,c,m]
// ============================================================================
__global__ __launch_bounds__(256) void delta_pre(const float* __restrict__ pos,
                                                 const float* __restrict__ epos,
                                                 const unsigned char* __restrict__ pmask,
                                                 const unsigned char* __restrict__ emask,
                                                 float* __restrict__ delta)
{
    int i = blockIdx.x * 256 + threadIdx.x;
    int m = i % NEXT;
    int n = (i / NEXT) % NN;
    int b = i / (NEXT * NN);

    float pxn = pos[(b * NN + n) * 3 + 0];
    float pyn = pos[(b * NN + n) * 3 + 1];
    float pzn = pos[(b * NN + n) * 3 + 2];
    bool  pn  = pmask[b * NN + n] != 0;

    float ax, ay, az; bool fm;
    if (m < NN) {
        const float* pp = pos + (b * NN + m) * 3;
        ax = pp[0]; ay = pp[1]; az = pp[2];
        fm = pmask[b * NN + m] != 0;
    } else {
        const float* pp = epos + (b * NM + m - NN) * 3;
        ax = pp[0]; ay = pp[1]; az = pp[2];
        fm = emask[b * NM + m - NN] != 0;
    }
    float dx = pxn - ax, dy = pyn - ay, dz = pzn - az;
    float dist = sqrt_approx(dx * dx + dy * dy + dz * dz);
    if (pn || fm) dist = 1e6f;
    float inv = rcp_approx(dist + 1.f);
    if (pn) inv = 0.f;

    size_t base = ((size_t)(b * NN + n) * 3) * NEXT + m;
    delta[base           ] = dx * inv;
    delta[base +     NEXT] = dy * inv;
    delta[base + 2 * NEXT] = dz * inv;
}

// ============================================================================
// Tensor-core split-precision GEMM, 64x128 CTA tile, 3 CTAs/SM.
// ============================================================================
#define T64_A    2560
#define T64_B    5120
#define STG64    15360
#define GSMEM_BYTES 61440

__global__ __launch_bounds__(256, 3) void gemm_mma(const __nv_bfloat16* __restrict__ Ah,
                                                   const __nv_bfloat16* __restrict__ Al,
                                                   const __nv_bfloat16* __restrict__ Bh,
                                                   const __nv_bfloat16* __restrict__ Bl,
                                                   const __nv_bfloat16* __restrict__ Bh2,
                                                   const __nv_bfloat16* __restrict__ Bl2,
                                                   int ysplit,
                                                   float* __restrict__ C,
                                                   __nv_bfloat16* __restrict__ Ch,
                                                   __nv_bfloat16* __restrict__ Cl,
                                                   float alpha0, int mode)
{
    extern __shared__ __nv_bfloat16 sm[];

    const int tid  = threadIdx.x;
    const int wid  = tid >> 5;
    const int lane = tid & 31;
    const int g    = lane >> 2;
    const int tig  = lane & 3;
    const int row0 = blockIdx.y << 6;
    const int col0 = blockIdx.x << 7;
    const int z    = blockIdx.z;
    if ((int)blockIdx.y >= ysplit) { Bh = Bh2; Bl = Bl2; }
    Bh += (size_t)z << 20;
    Bl += (size_t)z << 20;
    if (mode == 0) C += (size_t)z << 21;
    else { Ch += (size_t)z << 21; Cl += (size_t)z << 21; }
    const float alpha = (z == 0) ? alpha0 : 1.0f;
    const int wm = (wid & 1) << 5;
    const int wn = (wid >> 1) << 5;

    float acc[2][4][4];
    #pragma unroll
    for (int i = 0; i < 2; i++)
        #pragma unroll
        for (int j = 0; j < 4; j++)
            #pragma unroll
            for (int q = 0; q < 4; q++) acc[i][j][q] = 0.f;

    const uint32_t smbase = smem_u32(sm);
    const uint32_t a_off = ((wm + (lane & 7) + (((lane >> 3) & 1) << 3)) * 40
                            + ((lane >> 4) << 3)) * 2;
    const uint32_t b_off = ((wn + (lane & 7) + ((lane >> 4) << 3)) * 40
                            + (((lane >> 3) & 1) << 3)) * 2;

    #define LOAD_CHUNK(kc, s)                                                     \
    {                                                                             \
        _Pragma("unroll")                                                         \
        for (int t = 0; t < 6; t++) {                                             \
            int u  = tid + (t << 8);                                              \
            int r  = u >> 2;                                                      \
            int cu = u & 3;                                                       \
            const __nv_bfloat16* gp;                                              \
            uint32_t selem;                                                       \
            if (r < 64)       { gp = Ah + (size_t)(row0 + r) * 1024;              \
                                selem = r * 40; }                                 \
            else if (r < 128) { gp = Al + (size_t)(row0 + r - 64) * 1024;         \
                                selem = T64_A + (r - 64) * 40; }                  \
            else if (r < 256) { gp = Bh + (size_t)(col0 + r - 128) * 1024;        \
                                selem = 2 * T64_A + (r - 128) * 40; }             \
            else              { gp = Bl + (size_t)(col0 + r - 256) * 1024;        \
                                selem = 2 * T64_A + T64_B + (r - 256) * 40; }     \
            gp += (kc) * 32 + cu * 8;                                             \
            uint32_t sa = smbase + ((s) * STG64 + selem + cu * 8) * 2;            \
            CP_ASYNC16(sa, gp);                                                   \
        }                                                                         \
    }

    LOAD_CHUNK(0, 0);
    CP_COMMIT();

    for (int kc = 0; kc < 32; kc++) {
        CP_WAIT(0);
        __syncthreads();
        if (kc + 1 < 32) {
            LOAD_CHUNK(kc + 1, (kc + 1) & 1);
            CP_COMMIT();
        }

        const uint32_t so2 = (kc & 1) * (STG64 * 2);
        const uint32_t abase = smbase + so2 + a_off;
        const uint32_t bbase = smbase + so2 + 2 * T64_A * 2 + b_off;

        #pragma unroll
        for (int kk = 0; kk < 2; kk++) {
            const uint32_t kwb = kk << 5;
            uint32_t ah[2][4], al[2][4], bh[4][2], bl[4][2];
            #pragma unroll
            for (int i = 0; i < 2; i++) {
                ldsm4(ah[i][0], ah[i][1], ah[i][2], ah[i][3],
                      abase + i * 1280 + kwb);
                ldsm4(al[i][0], al[i][1], al[i][2], al[i][3],
                      abase + T64_A * 2 + i * 1280 + kwb);
            }
            #pragma unroll
            for (int jp = 0; jp < 2; jp++) {
                ldsm4(bh[2*jp][0], bh[2*jp][1], bh[2*jp+1][0], bh[2*jp+1][1],
                      bbase + jp * 1280 + kwb);
                ldsm4(bl[2*jp][0], bl[2*jp][1], bl[2*jp+1][0], bl[2*jp+1][1],
                      bbase + T64_B * 2 + jp * 1280 + kwb);
            }
            #pragma unroll
            for (int i = 0; i < 2; i++)
                #pragma unroll
                for (int j = 0; j < 4; j++)
                    mma16816(acc[i][j], ah[i], bh[j]);
            #pragma unroll
            for (int i = 0; i < 2; i++)
                #pragma unroll
                for (int j = 0; j < 4; j++)
                    mma16816(acc[i][j], ah[i], bl[j]);
            #pragma unroll
            for (int i = 0; i < 2; i++)
                #pragma unroll
                for (int j = 0; j < 4; j++)
                    mma16816(acc[i][j], al[i], bh[j]);
        }
    }

    #pragma unroll
    for (int i = 0; i < 2; i++) {
        int row = row0 + wm + (i << 4) + g;
        #pragma unroll
        for (int j = 0; j < 4; j++) {
            int col = col0 + wn + (j << 3) + (tig << 1);
            float v0 = alpha * acc[i][j][0];
            float v1 = alpha * acc[i][j][1];
            float v2 = alpha * acc[i][j][2];
            float v3 = alpha * acc[i][j][3];
            if (mode == 0) {
                *(float2*)(C + (size_t)row * 1024 + col)       = make_float2(v0, v1);
                *(float2*)(C + (size_t)(row + 8) * 1024 + col) = make_float2(v2, v3);
            } else {
                uint32_t h0, l0, h1, l1;
                split2(v0, v1, h0, l0);
                split2(v2, v3, h1, l1);
                *(uint32_t*)(Ch + (size_t)row * 1024 + col)       = h0;
                *(uint32_t*)(Cl + (size_t)row * 1024 + col)       = l0;
                *(uint32_t*)(Ch + (size_t)(row + 8) * 1024 + col) = h1;
                *(uint32_t*)(Cl + (size_t)(row + 8) * 1024 + col) = l1;
            }
        }
    }
}

// ============================================================================
// Fused QK^T + bias + mask + softmax (32-row tile, 2 CTA/SM, __expf)
// ============================================================================
#define LSTRIDE 772
#define QK_SMEM 114176

__global__ __launch_bounds__(256, 2) void qk_softmax(const float* __restrict__ bias,
                                                  const int*   __restrict__ oidx,
                                                  const unsigned char* __restrict__ pmask,
                                                  const unsigned char* __restrict__ emask,
                                                  const __nv_bfloat16* __restrict__ qh_g,
                                                  const __nv_bfloat16* __restrict__ ql_g,
                                                  const __nv_bfloat16* __restrict__ kh_g,
                                                  const __nv_bfloat16* __restrict__ kl_g)
{
    extern __shared__ char sraw[];
    __nv_bfloat16* sqh = (__nv_bfloat16*)sraw;
    __nv_bfloat16* sql = sqh + 1280;
    __nv_bfloat16* skh = sqh + 2560;
    __nv_bfloat16* skl = sqh + 5120;
    float* logits = (float*)(sraw + 15360);

    const int tid  = threadIdx.x;
    const int wid  = tid >> 5;
    const int lane = tid & 31;
    const int g    = lane >> 2;
    const int tig  = lane & 3;
    const int bh   = blockIdx.y;
    const int b    = bh >> 5;
    const int h    = bh & 31;
    const int n0   = blockIdx.x << 5;

    if (tid < 128) {
        int r = tid >> 2, c = (tid & 3) << 3;
        size_t off = (size_t)(b * NN + n0 + r) * NE + h * ND + c;
        *(uint4*)(sqh + r * 40 + c) = *(const uint4*)(qh_g + off);
        *(uint4*)(sql + r * 40 + c) = *(const uint4*)(ql_g + off);
    }

    const int wn = (wid & 1) << 4;
    const int wm = (wid >> 1) << 4;

    for (int m0 = 0; m0 < NEXT; m0 += 64) {
        __syncthreads();
        {
            int r = tid >> 2, c = (tid & 3) << 3;
            int m = m0 + r;
            int row = (m < NN) ? m : oidx[b * NM + m - NN];
            size_t off = (size_t)(b * NN + row) * NE + h * ND + c;
            *(uint4*)(skh + r * 40 + c) = *(const uint4*)(kh_g + off);
            *(uint4*)(skl + r * 40 + c) = *(const uint4*)(kl_g + off);
        }
        __syncthreads();

        float acc[2][4];
        #pragma unroll
        for (int j = 0; j < 2; j++)
            #pragma unroll
            for (int q = 0; q < 4; q++) acc[j][q] = 0.f;

        #pragma unroll
        for (int kk = 0; kk < 2; kk++) {
            const int kw = kk << 3;
            uint32_t a_h[4], a_l[4], bhf[2][2], blf[2][2];
            {
                int rA = wn + g;
                a_h[0] = *(const uint32_t*)(sqh + (rA    ) * 40 + ((kw + tig    ) << 1));
                a_h[1] = *(const uint32_t*)(sqh + (rA + 8) * 40 + ((kw + tig    ) << 1));
                a_h[2] = *(const uint32_t*)(sqh + (rA    ) * 40 + ((kw + tig + 4) << 1));
                a_h[3] = *(const uint32_t*)(sqh + (rA + 8) * 40 + ((kw + tig + 4) << 1));
                a_l[0] = *(const uint32_t*)(sql + (rA    ) * 40 + ((kw + tig    ) << 1));
                a_l[1] = *(const uint32_t*)(sql + (rA + 8) * 40 + ((kw + tig    ) << 1));
                a_l[2] = *(const uint32_t*)(sql + (rA    ) * 40 + ((kw + tig + 4) << 1));
                a_l[3] = *(const uint32_t*)(sql + (rA + 8) * 40 + ((kw + tig + 4) << 1));
            }
            #pragma unroll
            for (int j = 0; j < 2; j++) {
                int rB = wm + (j << 3) + g;
                bhf[j][0] = *(const uint32_t*)(skh + rB * 40 + ((kw + tig    ) << 1));
                bhf[j][1] = *(const uint32_t*)(skh + rB * 40 + ((kw + tig + 4) << 1));
                blf[j][0] = *(const uint32_t*)(skl + rB * 40 + ((kw + tig    ) << 1));
                blf[j][1] = *(const uint32_t*)(skl + rB * 40 + ((kw + tig + 4) << 1));
            }
            #pragma unroll
            for (int j = 0; j < 2; j++) mma16816(acc[j], a_h, bhf[j]);
            #pragma unroll
            for (int j = 0; j < 2; j++) mma16816(acc[j], a_h, blf[j]);
            #pragma unroll
            for (int j = 0; j < 2; j++) mma16816(acc[j], a_l, bhf[j]);
        }

        #pragma unroll
        for (int j = 0; j < 2; j++) {
            int col = m0 + wm + (j << 3) + (tig << 1);
            int row = wn + g;
            *(float2*)&logits[row * LSTRIDE + col]       = make_float2(acc[j][0], acc[j][1]);
            *(float2*)&logits[(row + 8) * LSTRIDE + col] = make_float2(acc[j][2], acc[j][3]);
        }
    }
    __syncthreads();

    for (int rr = wid; rr < 32; rr += 8) {
        int n = n0 + rr;
        bool pn = pmask[b * NN + n] != 0;
        const float* lrow = logits + rr * LSTRIDE;
        long long goff = (((long long)(b * NH + h)) * NN + n) * NEXT;

        float val[24];
        float mx = -FLT_MAX;
        #pragma unroll
        for (int t = 0; t < 24; t++) {
            int m = lane + (t << 5);
            bool fm = (m < NN) ? (pmask[b * NN + m] != 0)
                               : (emask[b * NM + m - NN] != 0);
            float v = lrow[m] + bias[goff + m];
            if (pn || fm) v = -FLT_MAX;
            val[t] = v;
            mx = fmaxf(mx, v);
        }
        #pragma unroll
        for (int o = 16; o > 0; o >>= 1)
            mx = fmaxf(mx, __shfl_xor_sync(0xffffffffu, mx, o));
        float s = 0.f;
        #pragma unroll
        for (int t = 0; t < 24; t++) {
            val[t] = __expf(val[t] - mx);
            s += val[t];
        }
        #pragma unroll
        for (int o = 16; o > 0; o >>= 1)
            s += __shfl_xor_sync(0xffffffffu, s, o);
        float inv = 1.f / s;
        #pragma unroll
        for (int t = 0; t < 24; t++)
            g_attn[goff + lane + (t << 5)] = val[t] * inv;
    }
}

// ============================================================================
// Fused PV + vec, 32-row n-tile, 3 CTAs/SM.
//   One output per warp-pair: o_out = wid>>1 (xo,vx,vy,vz), rhalf = (wid&1)*16.
// smem (bf16 ele): A mats 8 x (32x72) = 18432, B mats 4 x (32x72) = 9216.
// ============================================================================
#define PV_A32   2304          // 32*72
#define PV_VB32  18432         // 8 * PV_A32
#define PV_B     2304          // 32*72 (d-major B mat)
#define PV_SMEM  55296         // (18432 + 9216) * 2 bytes

__global__ __launch_bounds__(256, 3) void pv_mma(const float* __restrict__ delta,
                                                 const int*   __restrict__ oidx,
                                                 const __nv_bfloat16* __restrict__ vh_g,
                                                 const __nv_bfloat16* __restrict__ vl_g,
                                                 const __nv_bfloat16* __restrict__ veh_g,
                                                 const __nv_bfloat16* __restrict__ vel_g,
                                                 __nv_bfloat16* __restrict__ outh,
                                                 __nv_bfloat16* __restrict__ outl)
{
    extern __shared__ __nv_bfloat16 sp[];

    const int tid  = threadIdx.x;
    const int wid  = tid >> 5;
    const int lane = tid & 31;
    const int g    = lane >> 2;
    const int tig  = lane & 3;
    const int b    = blockIdx.z;
    const int h    = blockIdx.y;
    const int n0   = blockIdx.x << 5;    // 32-row tile

    const int o_out = wid >> 1;          // 0=xo 1=vx 2=vy 3=vz
    const int rhalf = (wid & 1) << 4;    // 0 / 16

    __nv_bfloat16* VEh = sp + PV_VB32;
    __nv_bfloat16* VEl = VEh + PV_B;
    __nv_bfloat16* Vh  = VEh + 2 * PV_B;
    __nv_bfloat16* Vl  = VEh + 3 * PV_B;

    const uint32_t spb = smem_u32(sp);
    const uint32_t a_offp = ((rhalf + (lane & 7) + (((lane >> 3) & 1) << 3)) * 72
                             + ((lane >> 4) << 3)) * 2;
    const uint32_t b_offp = (((lane & 7) + ((lane >> 4) << 3)) * 72
                             + (((lane >> 3) & 1) << 3)) * 2;
    const uint32_t Auh = spb + (uint32_t)(2 * o_out * PV_A32) * 2 + a_offp;
    const uint32_t Aul = Auh + PV_A32 * 2;
    const uint32_t Buh = spb + (uint32_t)((o_out == 0) ? PV_VB32
                                                       : PV_VB32 + 2 * PV_B) * 2 + b_offp;
    const uint32_t Bul = Buh + PV_B * 2;

    float acc[4][4];
    #pragma unroll
    for (int j = 0; j < 4; j++)
        #pragma unroll
        for (int q = 0; q < 4; q++) acc[j][q] = 0.f;

    const int p_n  = tid >> 3;           // 0..31
    const int p_mb = (tid & 7) << 3;     // 0..56 (8 m per thread)
    const size_t drow = ((size_t)(b * NN + n0 + p_n) * 3) * NEXT;

    for (int m0 = 0; m0 < NEXT; m0 += 64) {
        __syncthreads();
        // ---- phase 1a: P * delta -> 4 scaled A mats (hi/lo) ----
        {
            const float* prow = g_attn +
                (((long long)(b * NH + h)) * NN + n0 + p_n) * NEXT + m0 + p_mb;
            float P[8], dxv[8], dyv[8], dzv[8];
            #pragma unroll
            for (int q4 = 0; q4 < 2; q4++) {
                *(float4*)(P   + q4*4) = *(const float4*)(prow + q4*4);
                *(float4*)(dxv + q4*4) = *(const float4*)(delta + drow            + m0 + p_mb + q4*4);
                *(float4*)(dyv + q4*4) = *(const float4*)(delta + drow +     NEXT + m0 + p_mb + q4*4);
                *(float4*)(dzv + q4*4) = *(const float4*)(delta + drow + 2 * NEXT + m0 + p_mb + q4*4);
            }
            int base = p_n * 72 + p_mb;
            #pragma unroll
            for (int qp = 0; qp < 4; qp++) {
                float p0 = P[2*qp], p1 = P[2*qp+1];
                uint32_t hi, lo;
                split2(p0, p1, hi, lo);
                *(uint32_t*)(sp + 0 * PV_A32 + base + 2*qp) = hi;
                *(uint32_t*)(sp + 1 * PV_A32 + base + 2*qp) = lo;
                split2(p0 * dxv[2*qp], p1 * dxv[2*qp+1], hi, lo);
                *(uint32_t*)(sp + 2 * PV_A32 + base + 2*qp) = hi;
                *(uint32_t*)(sp + 3 * PV_A32 + base + 2*qp) = lo;
                split2(p0 * dyv[2*qp], p1 * dyv[2*qp+1], hi, lo);
                *(uint32_t*)(sp + 4 * PV_A32 + base + 2*qp) = hi;
                *(uint32_t*)(sp + 5 * PV_A32 + base + 2*qp) = lo;
                split2(p0 * dzv[2*qp], p1 * dzv[2*qp+1], hi, lo);
                *(uint32_t*)(sp + 6 * PV_A32 + base + 2*qp) = hi;
                *(uint32_t*)(sp + 7 * PV_A32 + base + 2*qp) = lo;
            }
        }
        // ---- phase 1b: v / ve tiles (vectorized 16B gather) ----
        {
            #pragma unroll
            for (int t = 0; t < 4; t++) {
                int u    = tid + (t << 8);
                int m    = u & 63;
                int rest = u >> 6;
                int dq   = rest & 3;
                int mat  = rest >> 2;
                int mg   = m0 + m;
                int row  = (mg < NN) ? mg : oidx[b * NM + mg - NN];
                const __nv_bfloat16* gsrc = (mat == 0) ? veh_g
                                          : (mat == 1) ? vel_g
                                          : (mat == 2) ? vh_g : vl_g;
                __nv_bfloat16* dst = (mat == 0) ? VEh
                                   : (mat == 1) ? VEl
                                   : (mat == 2) ? Vh : Vl;
                uint4 v = *(const uint4*)(gsrc + (size_t)(b * NN + row) * NE
                                          + h * ND + (dq << 3));
                __nv_bfloat16 tmp[8];
                *(uint4*)tmp = v;
                #pragma unroll
                for (int s = 0; s < 8; s++)
                    dst[((dq << 3) + s) * 72 + m] = tmp[s];
            }
        }
        __syncthreads();

        // ---- phase 2: MMAs ----
        #pragma unroll
        for (int kk = 0; kk < 4; kk++) {
            const uint32_t kwb = kk << 5;
            uint32_t ah[4], al[4], bh[4][2], bl[4][2];
            ldsm4(ah[0], ah[1], ah[2], ah[3], Auh + kwb);
            ldsm4(al[0], al[1], al[2], al[3], Aul + kwb);
            #pragma unroll
            for (int jp = 0; jp < 2; jp++) {
                ldsm4(bh[2*jp][0], bh[2*jp][1], bh[2*jp+1][0], bh[2*jp+1][1],
                      Buh + jp * 2304 + kwb);
                ldsm4(bl[2*jp][0], bl[2*jp][1], bl[2*jp+1][0], bl[2*jp+1][1],
                      Bul + jp * 2304 + kwb);
            }
            #pragma unroll
            for (int j = 0; j < 4; j++) mma16816(acc[j], ah, bh[j]);
            #pragma unroll
            for (int j = 0; j < 4; j++) mma16816(acc[j], ah, bl[j]);
            #pragma unroll
            for (int j = 0; j < 4; j++) mma16816(acc[j], al, bh[j]);
        }
    }

    // ---- epilogue: one output per warp ----
    const int r0g = n0 + rhalf + g;
    #pragma unroll
    for (int j = 0; j < 4; j++) {
        int col = h * ND + (j << 3) + (tig << 1);
        size_t d0, d1;
        if (o_out == 0) {
            d0 = (size_t)(b * NN + r0g) * NE + col;
            d1 = (size_t)(b * NN + r0g + 8) * NE + col;
        } else {
            d0 = VOFF + ((size_t)(b * NN + r0g) * 3 + (o_out - 1)) * NE + col;
            d1 = VOFF + ((size_t)(b * NN + r0g + 8) * 3 + (o_out - 1)) * NE + col;
        }
        uint32_t hi, lo;
        split2(acc[j][0], acc[j][1], hi, lo);
        *(uint32_t*)(outh + d0) = hi; *(uint32_t*)(outl + d0) = lo;
        split2(acc[j][2], acc[j][3], hi, lo);
        *(uint32_t*)(outh + d1) = hi; *(uint32_t*)(outl + d1) = lo;
    }
}

// ============================================================================
// launch
// ============================================================================
extern "C" void kernel_launch(void* const* d_in, const int* in_sizes, int n_in,
                              void* d_out, int out_size)
{
    const float* x    = (const float*)d_in[0];
    const float* pos  = (const float*)d_in[1];
    const float* epos = (const float*)d_in[2];
    const float* bias = (const float*)d_in[3];
    const unsigned char* pmask = (const unsigned char*)d_in[4];
    const unsigned char* emask = (const unsigned char*)d_in[5];
    const int*   oidx = (const int*)d_in[6];
    const float* Wq   = (const float*)d_in[7];
    const float* Wk   = (const float*)d_in[8];
    const float* Wv   = (const float*)d_in[9];
    const float* Wve  = (const float*)d_in[10];
    const float* Wo   = (const float*)d_in[11];
    const float* Woe  = (const float*)d_in[12];
    float* out = (float*)d_out;

    __nv_bfloat16 *ah, *al, *wh, *wl, *ph, *pl;
    float *dlt;
    cudaGetSymbolAddress((void**)&ah,  g_ah);
    cudaGetSymbolAddress((void**)&al,  g_al);
    cudaGetSymbolAddress((void**)&wh,  g_wh);
    cudaGetSymbolAddress((void**)&wl,  g_wl);
    cudaGetSymbolAddress((void**)&ph,  g_projh);
    cudaGetSymbolAddress((void**)&pl,  g_projl);
    cudaGetSymbolAddress((void**)&dlt, g_delta);

    cudaFuncSetAttribute(gemm_mma,   cudaFuncAttributeMaxDynamicSharedMemorySize, GSMEM_BYTES);
    cudaFuncSetAttribute(qk_softmax, cudaFuncAttributeMaxDynamicSharedMemorySize, QK_SMEM);
    cudaFuncSetAttribute(pv_mma,     cudaFuncAttributeMaxDynamicSharedMemorySize, PV_SMEM);

    const int WSZ = 1024 * 1024;

    // 1) converters + delta precompute
    cvt_split_x<<<2048, 256>>>(x, ah, al);
    cvt_split_w<<<dim3(1024, 6), 256>>>(Wq, Wk, Wv, Wve, Woe, Wo, wh, wl);
    delta_pre<<<6144, 256>>>(pos, epos, pmask, emask, dlt);

    // 2) projections -> bf16 hi/lo (mode 1)
    gemm_mma<<<dim3(8, 32, 4), 256, GSMEM_BYTES>>>(ah, al, wh, wl,
                                                   nullptr, nullptr, 1024,
                                                   nullptr, ph, pl, SCALING_F, 1);

    // 3) fused QK + softmax
    qk_softmax<<<dim3(8, 256), 256, QK_SMEM>>>(bias, oidx, pmask, emask,
                                               ph, pl, ph + PSZ, pl + PSZ);

    // 4) fused PV + vec (32-row tiles, 3 CTA/SM)
    pv_mma<<<dim3(8, 32, 8), 256, PV_SMEM>>>(dlt, oidx,
                                             ph + 2*PSZ, pl + 2*PSZ,
                                             ph + 3*PSZ, pl + 3*PSZ,
                                             ah, al);

    // 5) fused output GEMMs
    gemm_mma<<<dim3(8, 128, 1), 256, GSMEM_BYTES>>>(ah, al,
                                                    wh + 4*WSZ, wl + 4*WSZ,
                                                    wh + 5*WSZ, wl + 5*WSZ, 32,
                                                    out, nullptr, nullptr, 1.0f, 0);
}

// round 14
// speedup vs baseline: 1.0220x; 1.0220x over previous
#include <cuda_runtime.h>
#include <cuda_bf16.h>
#include <float.h>
#include <math.h>
#include <stdint.h>

// Problem constants
#define NB 8
#define NN 256
#define NM 512
#define NE 1024
#define NH 32
#define ND 32
#define NEXT 768   // N + M

#define SCALING_F 0.17677669529663687f  // 32^-0.5

// ---------------- device scratch ----------------
static __device__ float g_attn[(long long)NB*NH*NN*NEXT];   // probs (fp32)
static __device__ float g_delta[(long long)NB*NN*3*NEXT];   // masked delta [b,n,c,m]
static __device__ __nv_bfloat16 g_ah[8192LL*1024];
static __device__ __nv_bfloat16 g_al[8192LL*1024];
static __device__ __nv_bfloat16 g_wh[6LL*1024*1024];
static __device__ __nv_bfloat16 g_wl[6LL*1024*1024];
static __device__ __nv_bfloat16 g_projh[4LL*2048*1024];
static __device__ __nv_bfloat16 g_projl[4LL*2048*1024];
#define PSZ 2097152
#define VOFF 2097152

// ============================================================================
// helpers
// ============================================================================
__device__ __forceinline__ uint32_t smem_u32(const void* p) {
    uint32_t a;
    asm("{ .reg .u64 t; cvta.to.shared.u64 t, %1; cvt.u32.u64 %0, t; }"
        : "=r"(a) : "l"(p));
    return a;
}
#define CP_ASYNC16(sa, ga) \
    asm volatile("cp.async.cg.shared.global [%0], [%1], 16;\n" :: "r"(sa), "l"(ga))
#define CP_COMMIT() asm volatile("cp.async.commit_group;\n" ::: "memory")
#define CP_WAIT(n)  asm volatile("cp.async.wait_group %0;\n" :: "n"(n) : "memory")

__device__ __forceinline__ void mma16816(float* c, const uint32_t* a, const uint32_t* b) {
    asm volatile(
        "mma.sync.aligned.m16n8k16.row.col.f32.bf16.bf16.f32 "
        "{%0,%1,%2,%3}, {%4,%5,%6,%7}, {%8,%9}, {%0,%1,%2,%3};\n"
        : "+f"(c[0]), "+f"(c[1]), "+f"(c[2]), "+f"(c[3])
        : "r"(a[0]), "r"(a[1]), "r"(a[2]), "r"(a[3]), "r"(b[0]), "r"(b[1]));
}
__device__ __forceinline__ void ldsm4(uint32_t& r0, uint32_t& r1, uint32_t& r2,
                                      uint32_t& r3, uint32_t a) {
    asm volatile("ldmatrix.sync.aligned.m8n8.x4.shared.b16 {%0,%1,%2,%3}, [%4];"
                 : "=r"(r0), "=r"(r1), "=r"(r2), "=r"(r3) : "r"(a));
}
// fast split (bit-identical rn rounding)
__device__ __forceinline__ void split2(float a, float b, uint32_t& hi, uint32_t& lo) {
    asm("cvt.rn.bf16x2.f32 %0, %1, %2;" : "=r"(hi) : "f"(b), "f"(a));
    float ha = __uint_as_float(hi << 16);
    float hb = __uint_as_float(hi & 0xffff0000u);
    asm("cvt.rn.bf16x2.f32 %0, %1, %2;" : "=r"(lo) : "f"(b - hb), "f"(a - ha));
}
__device__ __forceinline__ float sqrt_approx(float x) {
    float r;
    asm("sqrt.approx.f32 %0, %1;" : "=f"(r) : "f"(x));
    return r;
}
__device__ __forceinline__ float rcp_approx(float x) {
    float r;
    asm("rcp.approx.f32 %0, %1;" : "=f"(r) : "f"(x));
    return r;
}

// ============================================================================
// Merged prep: x-convert (blocks 0..2047), weight-convert (2048..8191),
// delta precompute (8192..14335). All memory-streaming; one launch.
// ============================================================================
__global__ __launch_bounds__(256) void prep(const float* __restrict__ x,
                                            const float* __restrict__ W0,
                                            const float* __restrict__ W1,
                                            const float* __restrict__ W2,
                                            const float* __restrict__ W3,
                                            const float* __restrict__ W4,
                                            const float* __restrict__ W5,
                                            const float* __restrict__ pos,
                                            const float* __restrict__ epos,
                                            const unsigned char* __restrict__ pmask,
                                            const unsigned char* __restrict__ emask,
                                            __nv_bfloat16* __restrict__ ah,
                                            __nv_bfloat16* __restrict__ al,
                                            __nv_bfloat16* __restrict__ wh,
                                            __nv_bfloat16* __restrict__ wl,
                                            float* __restrict__ delta)
{
    int blk = blockIdx.x;
    if (blk < 2048) {
        // x [N,B,E] -> row-major [B*N, E] hi/lo
        int i = blk * 256 + threadIdx.x;
        int r  = i >> 8;
        int e4 = (i & 255) << 2;
        int b = r >> 8, n = r & 255;
        float4 v = *(const float4*)(x + ((long long)n * NB + b) * NE + e4);
        uint32_t h0, l0, h1, l1;
        split2(v.x, v.y, h0, l0);
        split2(v.z, v.w, h1, l1);
        ((uint2*)ah)[i] = make_uint2(h0, h1);
        ((uint2*)al)[i] = make_uint2(l0, l1);
    } else if (blk < 8192) {
        int wsel = (blk - 2048) >> 10;
        const float* src = (wsel == 0) ? W0 : (wsel == 1) ? W1 : (wsel == 2) ? W2
                         : (wsel == 3) ? W3 : (wsel == 4) ? W4 : W5;
        int i = ((blk - 2048) & 1023) * 256 + threadIdx.x;
        float4 v = ((const float4*)src)[i];
        uint32_t h0, l0, h1, l1;
        split2(v.x, v.y, h0, l0);
        split2(v.z, v.w, h1, l1);
        size_t o = ((size_t)wsel << 18) + i;
        ((uint2*)wh)[o] = make_uint2(h0, h1);
        ((uint2*)wl)[o] = make_uint2(l0, l1);
    } else {
        int i = (blk - 8192) * 256 + threadIdx.x;
        int m = i % NEXT;
        int n = (i / NEXT) % NN;
        int b = i / (NEXT * NN);

        float pxn = pos[(b * NN + n) * 3 + 0];
        float pyn = pos[(b * NN + n) * 3 + 1];
        float pzn = pos[(b * NN + n) * 3 + 2];
        bool  pn  = pmask[b * NN + n] != 0;

        float ax, ay, az; bool fm;
        if (m < NN) {
            const float* pp = pos + (b * NN + m) * 3;
            ax = pp[0]; ay = pp[1]; az = pp[2];
            fm = pmask[b * NN + m] != 0;
        } else {
            const float* pp = epos + (b * NM + m - NN) * 3;
            ax = pp[0]; ay = pp[1]; az = pp[2];
            fm = emask[b * NM + m - NN] != 0;
        }
        float dx = pxn - ax, dy = pyn - ay, dz = pzn - az;
        float dist = sqrt_approx(dx * dx + dy * dy + dz * dz);
        if (pn || fm) dist = 1e6f;
        float inv = rcp_approx(dist + 1.f);
        if (pn) inv = 0.f;

        size_t base = ((size_t)(b * NN + n) * 3) * NEXT + m;
        delta[base           ] = dx * inv;
        delta[base +     NEXT] = dy * inv;
        delta[base + 2 * NEXT] = dz * inv;
    }
}

// ============================================================================
// Tensor-core split-precision GEMM, 64x128 CTA tile, 3 CTAs/SM.
// ============================================================================
#define T64_A    2560
#define T64_B    5120
#define STG64    15360
#define GSMEM_BYTES 61440

__global__ __launch_bounds__(256, 3) void gemm_mma(const __nv_bfloat16* __restrict__ Ah,
                                                   const __nv_bfloat16* __restrict__ Al,
                                                   const __nv_bfloat16* __restrict__ Bh,
                                                   const __nv_bfloat16* __restrict__ Bl,
                                                   const __nv_bfloat16* __restrict__ Bh2,
                                                   const __nv_bfloat16* __restrict__ Bl2,
                                                   int ysplit,
                                                   float* __restrict__ C,
                                                   __nv_bfloat16* __restrict__ Ch,
                                                   __nv_bfloat16* __restrict__ Cl,
                                                   float alpha0, int mode)
{
    extern __shared__ __nv_bfloat16 sm[];

    const int tid  = threadIdx.x;
    const int wid  = tid >> 5;
    const int lane = tid & 31;
    const int g    = lane >> 2;
    const int tig  = lane & 3;
    const int row0 = blockIdx.y << 6;
    const int col0 = blockIdx.x << 7;
    const int z    = blockIdx.z;
    if ((int)blockIdx.y >= ysplit) { Bh = Bh2; Bl = Bl2; }
    Bh += (size_t)z << 20;
    Bl += (size_t)z << 20;
    if (mode == 0) C += (size_t)z << 21;
    else { Ch += (size_t)z << 21; Cl += (size_t)z << 21; }
    const float alpha = (z == 0) ? alpha0 : 1.0f;
    const int wm = (wid & 1) << 5;
    const int wn = (wid >> 1) << 5;

    float acc[2][4][4];
    #pragma unroll
    for (int i = 0; i < 2; i++)
        #pragma unroll
        for (int j = 0; j < 4; j++)
            #pragma unroll
            for (int q = 0; q < 4; q++) acc[i][j][q] = 0.f;

    const uint32_t smbase = smem_u32(sm);
    const uint32_t a_off = ((wm + (lane & 7) + (((lane >> 3) & 1) << 3)) * 40
                            + ((lane >> 4) << 3)) * 2;
    const uint32_t b_off = ((wn + (lane & 7) + ((lane >> 4) << 3)) * 40
                            + (((lane >> 3) & 1) << 3)) * 2;

    #define LOAD_CHUNK(kc, s)                                                     \
    {                                                                             \
        _Pragma("unroll")                                                         \
        for (int t = 0; t < 6; t++) {                                             \
            int u  = tid + (t << 8);                                              \
            int r  = u >> 2;                                                      \
            int cu = u & 3;                                                       \
            const __nv_bfloat16* gp;                                              \
            uint32_t selem;                                                       \
            if (r < 64)       { gp = Ah + (size_t)(row0 + r) * 1024;              \
                                selem = r * 40; }                                 \
            else if (r < 128) { gp = Al + (size_t)(row0 + r - 64) * 1024;         \
                                selem = T64_A + (r - 64) * 40; }                  \
            else if (r < 256) { gp = Bh + (size_t)(col0 + r - 128) * 1024;        \
                                selem = 2 * T64_A + (r - 128) * 40; }             \
            else              { gp = Bl + (size_t)(col0 + r - 256) * 1024;        \
                                selem = 2 * T64_A + T64_B + (r - 256) * 40; }     \
            gp += (kc) * 32 + cu * 8;                                             \
            uint32_t sa = smbase + ((s) * STG64 + selem + cu * 8) * 2;            \
            CP_ASYNC16(sa, gp);                                                   \
        }                                                                         \
    }

    LOAD_CHUNK(0, 0);
    CP_COMMIT();

    for (int kc = 0; kc < 32; kc++) {
        CP_WAIT(0);
        __syncthreads();
        if (kc + 1 < 32) {
            LOAD_CHUNK(kc + 1, (kc + 1) & 1);
            CP_COMMIT();
        }

        const uint32_t so2 = (kc & 1) * (STG64 * 2);
        const uint32_t abase = smbase + so2 + a_off;
        const uint32_t bbase = smbase + so2 + 2 * T64_A * 2 + b_off;

        #pragma unroll
        for (int kk = 0; kk < 2; kk++) {
            const uint32_t kwb = kk << 5;
            uint32_t ah[2][4], al[2][4], bh[4][2], bl[4][2];
            #pragma unroll
            for (int i = 0; i < 2; i++) {
                ldsm4(ah[i][0], ah[i][1], ah[i][2], ah[i][3],
                      abase + i * 1280 + kwb);
                ldsm4(al[i][0], al[i][1], al[i][2], al[i][3],
                      abase + T64_A * 2 + i * 1280 + kwb);
            }
            #pragma unroll
            for (int jp = 0; jp < 2; jp++) {
                ldsm4(bh[2*jp][0], bh[2*jp][1], bh[2*jp+1][0], bh[2*jp+1][1],
                      bbase + jp * 1280 + kwb);
                ldsm4(bl[2*jp][0], bl[2*jp][1], bl[2*jp+1][0], bl[2*jp+1][1],
                      bbase + T64_B * 2 + jp * 1280 + kwb);
            }
            #pragma unroll
            for (int i = 0; i < 2; i++)
                #pragma unroll
                for (int j = 0; j < 4; j++)
                    mma16816(acc[i][j], ah[i], bh[j]);
            #pragma unroll
            for (int i = 0; i < 2; i++)
                #pragma unroll
                for (int j = 0; j < 4; j++)
                    mma16816(acc[i][j], ah[i], bl[j]);
            #pragma unroll
            for (int i = 0; i < 2; i++)
                #pragma unroll
                for (int j = 0; j < 4; j++)
                    mma16816(acc[i][j], al[i], bh[j]);
        }
    }

    #pragma unroll
    for (int i = 0; i < 2; i++) {
        int row = row0 + wm + (i << 4) + g;
        #pragma unroll
        for (int j = 0; j < 4; j++) {
            int col = col0 + wn + (j << 3) + (tig << 1);
            float v0 = alpha * acc[i][j][0];
            float v1 = alpha * acc[i][j][1];
            float v2 = alpha * acc[i][j][2];
            float v3 = alpha * acc[i][j][3];
            if (mode == 0) {
                *(float2*)(C + (size_t)row * 1024 + col)       = make_float2(v0, v1);
                *(float2*)(C + (size_t)(row + 8) * 1024 + col) = make_float2(v2, v3);
            } else {
                uint32_t h0, l0, h1, l1;
                split2(v0, v1, h0, l0);
                split2(v2, v3, h1, l1);
                *(uint32_t*)(Ch + (size_t)row * 1024 + col)       = h0;
                *(uint32_t*)(Cl + (size_t)row * 1024 + col)       = l0;
                *(uint32_t*)(Ch + (size_t)(row + 8) * 1024 + col) = h1;
                *(uint32_t*)(Cl + (size_t)(row + 8) * 1024 + col) = l1;
            }
        }
    }
}

// ============================================================================
// Fused QK^T + bias + mask + softmax (32-row tile, 2 CTA/SM, __expf)
// ============================================================================
#define LSTRIDE 772
#define QK_SMEM 114176

__global__ __launch_bounds__(256, 2) void qk_softmax(const float* __restrict__ bias,
                                                  const int*   __restrict__ oidx,
                                                  const unsigned char* __restrict__ pmask,
                                                  const unsigned char* __restrict__ emask,
                                                  const __nv_bfloat16* __restrict__ qh_g,
                                                  const __nv_bfloat16* __restrict__ ql_g,
                                                  const __nv_bfloat16* __restrict__ kh_g,
                                                  const __nv_bfloat16* __restrict__ kl_g)
{
    extern __shared__ char sraw[];
    __nv_bfloat16* sqh = (__nv_bfloat16*)sraw;
    __nv_bfloat16* sql = sqh + 1280;
    __nv_bfloat16* skh = sqh + 2560;
    __nv_bfloat16* skl = sqh + 5120;
    float* logits = (float*)(sraw + 15360);

    const int tid  = threadIdx.x;
    const int wid  = tid >> 5;
    const int lane = tid & 31;
    const int g    = lane >> 2;
    const int tig  = lane & 3;
    const int bh   = blockIdx.y;
    const int b    = bh >> 5;
    const int h    = bh & 31;
    const int n0   = blockIdx.x << 5;

    if (tid < 128) {
        int r = tid >> 2, c = (tid & 3) << 3;
        size_t off = (size_t)(b * NN + n0 + r) * NE + h * ND + c;
        *(uint4*)(sqh + r * 40 + c) = *(const uint4*)(qh_g + off);
        *(uint4*)(sql + r * 40 + c) = *(const uint4*)(ql_g + off);
    }

    const int wn = (wid & 1) << 4;
    const int wm = (wid >> 1) << 4;

    for (int m0 = 0; m0 < NEXT; m0 += 64) {
        __syncthreads();
        {
            int r = tid >> 2, c = (tid & 3) << 3;
            int m = m0 + r;
            int row = (m < NN) ? m : oidx[b * NM + m - NN];
            size_t off = (size_t)(b * NN + row) * NE + h * ND + c;
            *(uint4*)(skh + r * 40 + c) = *(const uint4*)(kh_g + off);
            *(uint4*)(skl + r * 40 + c) = *(const uint4*)(kl_g + off);
        }
        __syncthreads();

        float acc[2][4];
        #pragma unroll
        for (int j = 0; j < 2; j++)
            #pragma unroll
            for (int q = 0; q < 4; q++) acc[j][q] = 0.f;

        #pragma unroll
        for (int kk = 0; kk < 2; kk++) {
            const int kw = kk << 3;
            uint32_t a_h[4], a_l[4], bhf[2][2], blf[2][2];
            {
                int rA = wn + g;
                a_h[0] = *(const uint32_t*)(sqh + (rA    ) * 40 + ((kw + tig    ) << 1));
                a_h[1] = *(const uint32_t*)(sqh + (rA + 8) * 40 + ((kw + tig    ) << 1));
                a_h[2] = *(const uint32_t*)(sqh + (rA    ) * 40 + ((kw + tig + 4) << 1));
                a_h[3] = *(const uint32_t*)(sqh + (rA + 8) * 40 + ((kw + tig + 4) << 1));
                a_l[0] = *(const uint32_t*)(sql + (rA    ) * 40 + ((kw + tig    ) << 1));
                a_l[1] = *(const uint32_t*)(sql + (rA + 8) * 40 + ((kw + tig    ) << 1));
                a_l[2] = *(const uint32_t*)(sql + (rA    ) * 40 + ((kw + tig + 4) << 1));
                a_l[3] = *(const uint32_t*)(sql + (rA + 8) * 40 + ((kw + tig + 4) << 1));
            }
            #pragma unroll
            for (int j = 0; j < 2; j++) {
                int rB = wm + (j << 3) + g;
                bhf[j][0] = *(const uint32_t*)(skh + rB * 40 + ((kw + tig    ) << 1));
                bhf[j][1] = *(const uint32_t*)(skh + rB * 40 + ((kw + tig + 4) << 1));
                blf[j][0] = *(const uint32_t*)(skl + rB * 40 + ((kw + tig    ) << 1));
                blf[j][1] = *(const uint32_t*)(skl + rB * 40 + ((kw + tig + 4) << 1));
            }
            #pragma unroll
            for (int j = 0; j < 2; j++) mma16816(acc[j], a_h, bhf[j]);
            #pragma unroll
            for (int j = 0; j < 2; j++) mma16816(acc[j], a_h, blf[j]);
            #pragma unroll
            for (int j = 0; j < 2; j++) mma16816(acc[j], a_l, bhf[j]);
        }

        #pragma unroll
        for (int j = 0; j < 2; j++) {
            int col = m0 + wm + (j << 3) + (tig << 1);
            int row = wn + g;
            *(float2*)&logits[row * LSTRIDE + col]       = make_float2(acc[j][0], acc[j][1]);
            *(float2*)&logits[(row + 8) * LSTRIDE + col] = make_float2(acc[j][2], acc[j][3]);
        }
    }
    __syncthreads();

    for (int rr = wid; rr < 32; rr += 8) {
        int n = n0 + rr;
        bool pn = pmask[b * NN + n] != 0;
        const float* lrow = logits + rr * LSTRIDE;
        long long goff = (((long long)(b * NH + h)) * NN + n) * NEXT;

        float val[24];
        float mx = -FLT_MAX;
        #pragma unroll
        for (int t = 0; t < 24; t++) {
            int m = lane + (t << 5);
            bool fm = (m < NN) ? (pmask[b * NN + m] != 0)
                               : (emask[b * NM + m - NN] != 0);
            float v = lrow[m] + bias[goff + m];
            if (pn || fm) v = -FLT_MAX;
            val[t] = v;
            mx = fmaxf(mx, v);
        }
        #pragma unroll
        for (int o = 16; o > 0; o >>= 1)
            mx = fmaxf(mx, __shfl_xor_sync(0xffffffffu, mx, o));
        float s = 0.f;
        #pragma unroll
        for (int t = 0; t < 24; t++) {
            val[t] = __expf(val[t] - mx);
            s += val[t];
        }
        #pragma unroll
        for (int o = 16; o > 0; o >>= 1)
            s += __shfl_xor_sync(0xffffffffu, s, o);
        float inv = 1.f / s;
        #pragma unroll
        for (int t = 0; t < 24; t++)
            g_attn[goff + lane + (t << 5)] = val[t] * inv;
    }
}

// ============================================================================
// Fused PV + vec (R12 winner: 64-row tile, 2 CTA/SM, delta precomputed,
// vectorized gather, fast split2)
// ============================================================================
#define PV_A    4608
#define PV_VB   36864
#define PV_B    2304
#define PV_SMEM 92160

__global__ __launch_bounds__(256, 2) void pv_mma(const float* __restrict__ delta,
                                                 const int*   __restrict__ oidx,
                                                 const __nv_bfloat16* __restrict__ vh_g,
                                                 const __nv_bfloat16* __restrict__ vl_g,
                                                 const __nv_bfloat16* __restrict__ veh_g,
                                                 const __nv_bfloat16* __restrict__ vel_g,
                                                 __nv_bfloat16* __restrict__ outh,
                                                 __nv_bfloat16* __restrict__ outl)
{
    extern __shared__ __nv_bfloat16 sp[];

    const int tid  = threadIdx.x;
    const int wid  = tid >> 5;
    const int lane = tid & 31;
    const int g    = lane >> 2;
    const int tig  = lane & 3;
    const int b    = blockIdx.z;
    const int h    = blockIdx.y;
    const int n0   = blockIdx.x << 6;

    const int rowblk = (wid & 3) << 4;
    const int pair   = wid >> 2;

    __nv_bfloat16* VEh = sp + PV_VB;
    __nv_bfloat16* VEl = VEh + PV_B;
    __nv_bfloat16* Vh  = VEh + 2 * PV_B;
    __nv_bfloat16* Vl  = VEh + 3 * PV_B;

    const uint32_t spb = smem_u32(sp);
    const uint32_t a_offp = ((rowblk + (lane & 7) + (((lane >> 3) & 1) << 3)) * 72
                             + ((lane >> 4) << 3)) * 2;
    const uint32_t b_offp = (((lane & 7) + ((lane >> 4) << 3)) * 72
                             + (((lane >> 3) & 1) << 3)) * 2;
    const uint32_t A0u = spb + (((pair == 0) ? 0 : 4) * PV_A) * 2 + a_offp;
    const uint32_t A1u = spb + (((pair == 0) ? 2 : 6) * PV_A) * 2 + a_offp;
    const uint32_t Bvb = spb + PV_VB * 2;
    const uint32_t B0u = ((pair == 0) ? Bvb : Bvb + 2 * PV_B * 2) + b_offp;
    const uint32_t B1u = Bvb + 2 * PV_B * 2 + b_offp;

    float acc0[4][4], acc1[4][4];
    #pragma unroll
    for (int j = 0; j < 4; j++)
        #pragma unroll
        for (int q = 0; q < 4; q++) { acc0[j][q] = 0.f; acc1[j][q] = 0.f; }

    const int p_n  = tid >> 2;
    const int p_mb = (tid & 3) << 4;
    const size_t drow = ((size_t)(b * NN + n0 + p_n) * 3) * NEXT;

    for (int m0 = 0; m0 < NEXT; m0 += 64) {
        __syncthreads();
        // ---- phase 1a ----
        {
            const float* prow = g_attn +
                (((long long)(b * NH + h)) * NN + n0 + p_n) * NEXT + m0 + p_mb;
            float P[16], dxv[16], dyv[16], dzv[16];
            #pragma unroll
            for (int q4 = 0; q4 < 4; q4++) {
                *(float4*)(P   + q4*4) = *(const float4*)(prow + q4*4);
                *(float4*)(dxv + q4*4) = *(const float4*)(delta + drow            + m0 + p_mb + q4*4);
                *(float4*)(dyv + q4*4) = *(const float4*)(delta + drow +     NEXT + m0 + p_mb + q4*4);
                *(float4*)(dzv + q4*4) = *(const float4*)(delta + drow + 2 * NEXT + m0 + p_mb + q4*4);
            }
            int base = p_n * 72 + p_mb;
            #pragma unroll
            for (int qp = 0; qp < 8; qp++) {
                float p0 = P[2*qp], p1 = P[2*qp+1];
                uint32_t hi, lo;
                split2(p0, p1, hi, lo);
                *(uint32_t*)(sp + 0 * PV_A + base + 2*qp) = hi;
                *(uint32_t*)(sp + 1 * PV_A + base + 2*qp) = lo;
                split2(p0 * dxv[2*qp], p1 * dxv[2*qp+1], hi, lo);
                *(uint32_t*)(sp + 2 * PV_A + base + 2*qp) = hi;
                *(uint32_t*)(sp + 3 * PV_A + base + 2*qp) = lo;
                split2(p0 * dyv[2*qp], p1 * dyv[2*qp+1], hi, lo);
                *(uint32_t*)(sp + 4 * PV_A + base + 2*qp) = hi;
                *(uint32_t*)(sp + 5 * PV_A + base + 2*qp) = lo;
                split2(p0 * dzv[2*qp], p1 * dzv[2*qp+1], hi, lo);
                *(uint32_t*)(sp + 6 * PV_A + base + 2*qp) = hi;
                *(uint32_t*)(sp + 7 * PV_A + base + 2*qp) = lo;
            }
        }
        // ---- phase 1b ----
        {
            #pragma unroll
            for (int t = 0; t < 4; t++) {
                int u    = tid + (t << 8);
                int m    = u & 63;
                int rest = u >> 6;
                int dq   = rest & 3;
                int mat  = rest >> 2;
                int mg   = m0 + m;
                int row  = (mg < NN) ? mg : oidx[b * NM + mg - NN];
                const __nv_bfloat16* gsrc = (mat == 0) ? veh_g
                                          : (mat == 1) ? vel_g
                                          : (mat == 2) ? vh_g : vl_g;
                __nv_bfloat16* dst = (mat == 0) ? VEh
                                   : (mat == 1) ? VEl
                                   : (mat == 2) ? Vh : Vl;
                uint4 v = *(const uint4*)(gsrc + (size_t)(b * NN + row) * NE
                                          + h * ND + (dq << 3));
                __nv_bfloat16 tmp[8];
                *(uint4*)tmp = v;
                #pragma unroll
                for (int s = 0; s < 8; s++)
                    dst[((dq << 3) + s) * 72 + m] = tmp[s];
            }
        }
        __syncthreads();

        // ---- phase 2 ----
        #pragma unroll
        for (int o = 0; o < 2; o++) {
            const uint32_t Au = o ? A1u : A0u;
            const uint32_t Bu = o ? B1u : B0u;
            float (*acc)[4] = o ? acc1 : acc0;
            #pragma unroll
            for (int kk = 0; kk < 4; kk++) {
                const uint32_t kwb = kk << 5;
                uint32_t ah[4], al[4], bh[4][2], bl[4][2];
                ldsm4(ah[0], ah[1], ah[2], ah[3], Au + kwb);
                ldsm4(al[0], al[1], al[2], al[3], Au + PV_A * 2 + kwb);
                #pragma unroll
                for (int jp = 0; jp < 2; jp++) {
                    ldsm4(bh[2*jp][0], bh[2*jp][1], bh[2*jp+1][0], bh[2*jp+1][1],
                          Bu + jp * 2304 + kwb);
                    ldsm4(bl[2*jp][0], bl[2*jp][1], bl[2*jp+1][0], bl[2*jp+1][1],
                          Bu + PV_B * 2 + jp * 2304 + kwb);
                }
                #pragma unroll
                for (int j = 0; j < 4; j++) mma16816(acc[j], ah, bh[j]);
                #pragma unroll
                for (int j = 0; j < 4; j++) mma16816(acc[j], ah, bl[j]);
                #pragma unroll
                for (int j = 0; j < 4; j++) mma16816(acc[j], al, bh[j]);
            }
        }
    }

    // ---- epilogue ----
    const int r0g = n0 + rowblk + g;
    #pragma unroll
    for (int j = 0; j < 4; j++) {
        int col = h * ND + (j << 3) + (tig << 1);
        uint32_t hi, lo;
        if (pair == 0) {
            size_t ro0 = (size_t)(b * NN + r0g) * NE + col;
            size_t ro1 = (size_t)(b * NN + r0g + 8) * NE + col;
            split2(acc0[j][0], acc0[j][1], hi, lo);
            *(uint32_t*)(outh + ro0) = hi; *(uint32_t*)(outl + ro0) = lo;
            split2(acc0[j][2], acc0[j][3], hi, lo);
            *(uint32_t*)(outh + ro1) = hi; *(uint32_t*)(outl + ro1) = lo;
            size_t vo0 = VOFF + ((size_t)(b * NN + r0g) * 3 + 0) * NE + col;
            size_t vo1 = VOFF + ((size_t)(b * NN + r0g + 8) * 3 + 0) * NE + col;
            split2(acc1[j][0], acc1[j][1], hi, lo);
            *(uint32_t*)(outh + vo0) = hi; *(uint32_t*)(outl + vo0) = lo;
            split2(acc1[j][2], acc1[j][3], hi, lo);
            *(uint32_t*)(outh + vo1) = hi; *(uint32_t*)(outl + vo1) = lo;
        } else {
            size_t vo0 = VOFF + ((size_t)(b * NN + r0g) * 3 + 1) * NE + col;
            size_t vo1 = VOFF + ((size_t)(b * NN + r0g + 8) * 3 + 1) * NE + col;
            split2(acc0[j][0], acc0[j][1], hi, lo);
            *(uint32_t*)(outh + vo0) = hi; *(uint32_t*)(outl + vo0) = lo;
            split2(acc0[j][2], acc0[j][3], hi, lo);
            *(uint32_t*)(outh + vo1) = hi; *(uint32_t*)(outl + vo1) = lo;
            size_t wo0 = VOFF + ((size_t)(b * NN + r0g) * 3 + 2) * NE + col;
            size_t wo1 = VOFF + ((size_t)(b * NN + r0g + 8) * 3 + 2) * NE + col;
            split2(acc1[j][0], acc1[j][1], hi, lo);
            *(uint32_t*)(outh + wo0) = hi; *(uint32_t*)(outl + wo0) = lo;
            split2(acc1[j][2], acc1[j][3], hi, lo);
            *(uint32_t*)(outh + wo1) = hi; *(uint32_t*)(outl + wo1) = lo;
        }
    }
}

// ============================================================================
// launch
// ============================================================================
extern "C" void kernel_launch(void* const* d_in, const int* in_sizes, int n_in,
                              void* d_out, int out_size)
{
    const float* x    = (const float*)d_in[0];
    const float* pos  = (const float*)d_in[1];
    const float* epos = (const float*)d_in[2];
    const float* bias = (const float*)d_in[3];
    const unsigned char* pmask = (const unsigned char*)d_in[4];
    const unsigned char* emask = (const unsigned char*)d_in[5];
    const int*   oidx = (const int*)d_in[6];
    const float* Wq   = (const float*)d_in[7];
    const float* Wk   = (const float*)d_in[8];
    const float* Wv   = (const float*)d_in[9];
    const float* Wve  = (const float*)d_in[10];
    const float* Wo   = (const float*)d_in[11];
    const float* Woe  = (const float*)d_in[12];
    float* out = (float*)d_out;

    __nv_bfloat16 *ah, *al, *wh, *wl, *ph, *pl;
    float *dlt;
    cudaGetSymbolAddress((void**)&ah,  g_ah);
    cudaGetSymbolAddress((void**)&al,  g_al);
    cudaGetSymbolAddress((void**)&wh,  g_wh);
    cudaGetSymbolAddress((void**)&wl,  g_wl);
    cudaGetSymbolAddress((void**)&ph,  g_projh);
    cudaGetSymbolAddress((void**)&pl,  g_projl);
    cudaGetSymbolAddress((void**)&dlt, g_delta);

    cudaFuncSetAttribute(gemm_mma,   cudaFuncAttributeMaxDynamicSharedMemorySize, GSMEM_BYTES);
    cudaFuncSetAttribute(qk_softmax, cudaFuncAttributeMaxDynamicSharedMemorySize, QK_SMEM);
    cudaFuncSetAttribute(pv_mma,     cudaFuncAttributeMaxDynamicSharedMemorySize, PV_SMEM);

    const int WSZ = 1024 * 1024;

    // 1) merged prep: x-convert + weight-convert + delta precompute
    prep<<<14336, 256>>>(x, Wq, Wk, Wv, Wve, Woe, Wo,
                         pos, epos, pmask, emask,
                         ah, al, wh, wl, dlt);

    // 2) projections -> bf16 hi/lo (mode 1)
    gemm_mma<<<dim3(8, 32, 4), 256, GSMEM_BYTES>>>(ah, al, wh, wl,
                                                   nullptr, nullptr, 1024,
                                                   nullptr, ph, pl, SCALING_F, 1);

    // 3) fused QK + softmax
    qk_softmax<<<dim3(8, 256), 256, QK_SMEM>>>(bias, oidx, pmask, emask,
                                               ph, pl, ph + PSZ, pl + PSZ);

    // 4) fused PV + vec (64-row tiles)
    pv_mma<<<dim3(4, 32, 8), 256, PV_SMEM>>>(dlt, oidx,
                                             ph + 2*PSZ, pl + 2*PSZ,
                                             ph + 3*PSZ, pl + 3*PSZ,
                                             ah, al);

    // 5) fused output GEMMs
    gemm_mma<<<dim3(8, 128, 1), 256, GSMEM_BYTES>>>(ah, al,
                                                    wh + 4*WSZ, wl + 4*WSZ,
                                                    wh + 5*WSZ, wl + 5*WSZ, 32,
                                                    out, nullptr, nullptr, 1.0f, 0);
}

// round 15
// speedup vs baseline: 1.0265x; 1.0044x over previous
#include <cuda_runtime.h>
#include <cuda_bf16.h>
#include <float.h>
#include <math.h>
#include <stdint.h>

// Problem constants
#define NB 8
#define NN 256
#define NM 512
#define NE 1024
#define NH 32
#define ND 32
#define NEXT 768   // N + M

#define SCALING_F 0.17677669529663687f  // 32^-0.5

// ---------------- device scratch ----------------
static __device__ float g_attn[(long long)NB*NH*NN*NEXT];   // probs (fp32)
static __device__ float g_delta[(long long)NB*NN*3*NEXT];   // masked delta [b,n,c,m]
static __device__ __nv_bfloat16 g_ah[8192LL*1024];
static __device__ __nv_bfloat16 g_al[8192LL*1024];
static __device__ __nv_bfloat16 g_wh[6LL*1024*1024];
static __device__ __nv_bfloat16 g_wl[6LL*1024*1024];
static __device__ __nv_bfloat16 g_projh[4LL*2048*1024];
static __device__ __nv_bfloat16 g_projl[4LL*2048*1024];
#define PSZ 2097152
#define VOFF 2097152

// ============================================================================
// helpers
// ============================================================================
__device__ __forceinline__ uint32_t smem_u32(const void* p) {
    uint32_t a;
    asm("{ .reg .u64 t; cvta.to.shared.u64 t, %1; cvt.u32.u64 %0, t; }"
        : "=r"(a) : "l"(p));
    return a;
}
#define CP_ASYNC16(sa, ga) \
    asm volatile("cp.async.cg.shared.global [%0], [%1], 16;\n" :: "r"(sa), "l"(ga))
#define CP_COMMIT() asm volatile("cp.async.commit_group;\n" ::: "memory")
#define CP_WAIT(n)  asm volatile("cp.async.wait_group %0;\n" :: "n"(n) : "memory")

__device__ __forceinline__ void mma16816(float* c, const uint32_t* a, const uint32_t* b) {
    asm volatile(
        "mma.sync.aligned.m16n8k16.row.col.f32.bf16.bf16.f32 "
        "{%0,%1,%2,%3}, {%4,%5,%6,%7}, {%8,%9}, {%0,%1,%2,%3};\n"
        : "+f"(c[0]), "+f"(c[1]), "+f"(c[2]), "+f"(c[3])
        : "r"(a[0]), "r"(a[1]), "r"(a[2]), "r"(a[3]), "r"(b[0]), "r"(b[1]));
}
__device__ __forceinline__ void ldsm4(uint32_t& r0, uint32_t& r1, uint32_t& r2,
                                      uint32_t& r3, uint32_t a) {
    asm volatile("ldmatrix.sync.aligned.m8n8.x4.shared.b16 {%0,%1,%2,%3}, [%4];"
                 : "=r"(r0), "=r"(r1), "=r"(r2), "=r"(r3) : "r"(a));
}
__device__ __forceinline__ void ldsm4t(uint32_t& r0, uint32_t& r1, uint32_t& r2,
                                       uint32_t& r3, uint32_t a) {
    asm volatile("ldmatrix.sync.aligned.m8n8.x4.trans.shared.b16 {%0,%1,%2,%3}, [%4];"
                 : "=r"(r0), "=r"(r1), "=r"(r2), "=r"(r3) : "r"(a));
}
// fast split (bit-identical rn rounding)
__device__ __forceinline__ void split2(float a, float b, uint32_t& hi, uint32_t& lo) {
    asm("cvt.rn.bf16x2.f32 %0, %1, %2;" : "=r"(hi) : "f"(b), "f"(a));
    float ha = __uint_as_float(hi << 16);
    float hb = __uint_as_float(hi & 0xffff0000u);
    asm("cvt.rn.bf16x2.f32 %0, %1, %2;" : "=r"(lo) : "f"(b - hb), "f"(a - ha));
}
__device__ __forceinline__ float sqrt_approx(float x) {
    float r;
    asm("sqrt.approx.f32 %0, %1;" : "=f"(r) : "f"(x));
    return r;
}
__device__ __forceinline__ float rcp_approx(float x) {
    float r;
    asm("rcp.approx.f32 %0, %1;" : "=f"(r) : "f"(x));
    return r;
}

// ============================================================================
// Merged prep: x-convert (blocks 0..2047), weight-convert (2048..8191),
// delta precompute (8192..14335).
// ============================================================================
__global__ __launch_bounds__(256) void prep(const float* __restrict__ x,
                                            const float* __restrict__ W0,
                                            const float* __restrict__ W1,
                                            const float* __restrict__ W2,
                                            const float* __restrict__ W3,
                                            const float* __restrict__ W4,
                                            const float* __restrict__ W5,
                                            const float* __restrict__ pos,
                                            const float* __restrict__ epos,
                                            const unsigned char* __restrict__ pmask,
                                            const unsigned char* __restrict__ emask,
                                            __nv_bfloat16* __restrict__ ah,
                                            __nv_bfloat16* __restrict__ al,
                                            __nv_bfloat16* __restrict__ wh,
                                            __nv_bfloat16* __restrict__ wl,
                                            float* __restrict__ delta)
{
    int blk = blockIdx.x;
    if (blk < 2048) {
        int i = blk * 256 + threadIdx.x;
        int r  = i >> 8;
        int e4 = (i & 255) << 2;
        int b = r >> 8, n = r & 255;
        float4 v = *(const float4*)(x + ((long long)n * NB + b) * NE + e4);
        uint32_t h0, l0, h1, l1;
        split2(v.x, v.y, h0, l0);
        split2(v.z, v.w, h1, l1);
        ((uint2*)ah)[i] = make_uint2(h0, h1);
        ((uint2*)al)[i] = make_uint2(l0, l1);
    } else if (blk < 8192) {
        int wsel = (blk - 2048) >> 10;
        const float* src = (wsel == 0) ? W0 : (wsel == 1) ? W1 : (wsel == 2) ? W2
                         : (wsel == 3) ? W3 : (wsel == 4) ? W4 : W5;
        int i = ((blk - 2048) & 1023) * 256 + threadIdx.x;
        float4 v = ((const float4*)src)[i];
        uint32_t h0, l0, h1, l1;
        split2(v.x, v.y, h0, l0);
        split2(v.z, v.w, h1, l1);
        size_t o = ((size_t)wsel << 18) + i;
        ((uint2*)wh)[o] = make_uint2(h0, h1);
        ((uint2*)wl)[o] = make_uint2(l0, l1);
    } else {
        int i = (blk - 8192) * 256 + threadIdx.x;
        int m = i % NEXT;
        int n = (i / NEXT) % NN;
        int b = i / (NEXT * NN);

        float pxn = pos[(b * NN + n) * 3 + 0];
        float pyn = pos[(b * NN + n) * 3 + 1];
        float pzn = pos[(b * NN + n) * 3 + 2];
        bool  pn  = pmask[b * NN + n] != 0;

        float ax, ay, az; bool fm;
        if (m < NN) {
            const float* pp = pos + (b * NN + m) * 3;
            ax = pp[0]; ay = pp[1]; az = pp[2];
            fm = pmask[b * NN + m] != 0;
        } else {
            const float* pp = epos + (b * NM + m - NN) * 3;
            ax = pp[0]; ay = pp[1]; az = pp[2];
            fm = emask[b * NM + m - NN] != 0;
        }
        float dx = pxn - ax, dy = pyn - ay, dz = pzn - az;
        float dist = sqrt_approx(dx * dx + dy * dy + dz * dz);
        if (pn || fm) dist = 1e6f;
        float inv = rcp_approx(dist + 1.f);
        if (pn) inv = 0.f;

        size_t base = ((size_t)(b * NN + n) * 3) * NEXT + m;
        delta[base           ] = dx * inv;
        delta[base +     NEXT] = dy * inv;
        delta[base + 2 * NEXT] = dz * inv;
    }
}

// ============================================================================
// Tensor-core split-precision GEMM, 64x128 CTA tile, 3 CTAs/SM.
// ============================================================================
#define T64_A    2560
#define T64_B    5120
#define STG64    15360
#define GSMEM_BYTES 61440

__global__ __launch_bounds__(256, 3) void gemm_mma(const __nv_bfloat16* __restrict__ Ah,
                                                   const __nv_bfloat16* __restrict__ Al,
                                                   const __nv_bfloat16* __restrict__ Bh,
                                                   const __nv_bfloat16* __restrict__ Bl,
                                                   const __nv_bfloat16* __restrict__ Bh2,
                                                   const __nv_bfloat16* __restrict__ Bl2,
                                                   int ysplit,
                                                   float* __restrict__ C,
                                                   __nv_bfloat16* __restrict__ Ch,
                                                   __nv_bfloat16* __restrict__ Cl,
                                                   float alpha0, int mode)
{
    extern __shared__ __nv_bfloat16 sm[];

    const int tid  = threadIdx.x;
    const int wid  = tid >> 5;
    const int lane = tid & 31;
    const int g    = lane >> 2;
    const int tig  = lane & 3;
    const int row0 = blockIdx.y << 6;
    const int col0 = blockIdx.x << 7;
    const int z    = blockIdx.z;
    if ((int)blockIdx.y >= ysplit) { Bh = Bh2; Bl = Bl2; }
    Bh += (size_t)z << 20;
    Bl += (size_t)z << 20;
    if (mode == 0) C += (size_t)z << 21;
    else { Ch += (size_t)z << 21; Cl += (size_t)z << 21; }
    const float alpha = (z == 0) ? alpha0 : 1.0f;
    const int wm = (wid & 1) << 5;
    const int wn = (wid >> 1) << 5;

    float acc[2][4][4];
    #pragma unroll
    for (int i = 0; i < 2; i++)
        #pragma unroll
        for (int j = 0; j < 4; j++)
            #pragma unroll
            for (int q = 0; q < 4; q++) acc[i][j][q] = 0.f;

    const uint32_t smbase = smem_u32(sm);
    const uint32_t a_off = ((wm + (lane & 7) + (((lane >> 3) & 1) << 3)) * 40
                            + ((lane >> 4) << 3)) * 2;
    const uint32_t b_off = ((wn + (lane & 7) + ((lane >> 4) << 3)) * 40
                            + (((lane >> 3) & 1) << 3)) * 2;

    #define LOAD_CHUNK(kc, s)                                                     \
    {                                                                             \
        _Pragma("unroll")                                                         \
        for (int t = 0; t < 6; t++) {                                             \
            int u  = tid + (t << 8);                                              \
            int r  = u >> 2;                                                      \
            int cu = u & 3;                                                       \
            const __nv_bfloat16* gp;                                              \
            uint32_t selem;                                                       \
            if (r < 64)       { gp = Ah + (size_t)(row0 + r) * 1024;              \
                                selem = r * 40; }                                 \
            else if (r < 128) { gp = Al + (size_t)(row0 + r - 64) * 1024;         \
                                selem = T64_A + (r - 64) * 40; }                  \
            else if (r < 256) { gp = Bh + (size_t)(col0 + r - 128) * 1024;        \
                                selem = 2 * T64_A + (r - 128) * 40; }             \
            else              { gp = Bl + (size_t)(col0 + r - 256) * 1024;        \
                                selem = 2 * T64_A + T64_B + (r - 256) * 40; }     \
            gp += (kc) * 32 + cu * 8;                                             \
            uint32_t sa = smbase + ((s) * STG64 + selem + cu * 8) * 2;            \
            CP_ASYNC16(sa, gp);                                                   \
        }                                                                         \
    }

    LOAD_CHUNK(0, 0);
    CP_COMMIT();

    for (int kc = 0; kc < 32; kc++) {
        CP_WAIT(0);
        __syncthreads();
        if (kc + 1 < 32) {
            LOAD_CHUNK(kc + 1, (kc + 1) & 1);
            CP_COMMIT();
        }

        const uint32_t so2 = (kc & 1) * (STG64 * 2);
        const uint32_t abase = smbase + so2 + a_off;
        const uint32_t bbase = smbase + so2 + 2 * T64_A * 2 + b_off;

        #pragma unroll
        for (int kk = 0; kk < 2; kk++) {
            const uint32_t kwb = kk << 5;
            uint32_t ah[2][4], al[2][4], bh[4][2], bl[4][2];
            #pragma unroll
            for (int i = 0; i < 2; i++) {
                ldsm4(ah[i][0], ah[i][1], ah[i][2], ah[i][3],
                      abase + i * 1280 + kwb);
                ldsm4(al[i][0], al[i][1], al[i][2], al[i][3],
                      abase + T64_A * 2 + i * 1280 + kwb);
            }
            #pragma unroll
            for (int jp = 0; jp < 2; jp++) {
                ldsm4(bh[2*jp][0], bh[2*jp][1], bh[2*jp+1][0], bh[2*jp+1][1],
                      bbase + jp * 1280 + kwb);
                ldsm4(bl[2*jp][0], bl[2*jp][1], bl[2*jp+1][0], bl[2*jp+1][1],
                      bbase + T64_B * 2 + jp * 1280 + kwb);
            }
            #pragma unroll
            for (int i = 0; i < 2; i++)
                #pragma unroll
                for (int j = 0; j < 4; j++)
                    mma16816(acc[i][j], ah[i], bh[j]);
            #pragma unroll
            for (int i = 0; i < 2; i++)
                #pragma unroll
                for (int j = 0; j < 4; j++)
                    mma16816(acc[i][j], ah[i], bl[j]);
            #pragma unroll
            for (int i = 0; i < 2; i++)
                #pragma unroll
                for (int j = 0; j < 4; j++)
                    mma16816(acc[i][j], al[i], bh[j]);
        }
    }

    #pragma unroll
    for (int i = 0; i < 2; i++) {
        int row = row0 + wm + (i << 4) + g;
        #pragma unroll
        for (int j = 0; j < 4; j++) {
            int col = col0 + wn + (j << 3) + (tig << 1);
            float v0 = alpha * acc[i][j][0];
            float v1 = alpha * acc[i][j][1];
            float v2 = alpha * acc[i][j][2];
            float v3 = alpha * acc[i][j][3];
            if (mode == 0) {
                *(float2*)(C + (size_t)row * 1024 + col)       = make_float2(v0, v1);
                *(float2*)(C + (size_t)(row + 8) * 1024 + col) = make_float2(v2, v3);
            } else {
                uint32_t h0, l0, h1, l1;
                split2(v0, v1, h0, l0);
                split2(v2, v3, h1, l1);
                *(uint32_t*)(Ch + (size_t)row * 1024 + col)       = h0;
                *(uint32_t*)(Cl + (size_t)row * 1024 + col)       = l0;
                *(uint32_t*)(Ch + (size_t)(row + 8) * 1024 + col) = h1;
                *(uint32_t*)(Cl + (size_t)(row + 8) * 1024 + col) = l1;
            }
        }
    }
}

// ============================================================================
// Fused QK^T + bias + mask + softmax (32-row tile, 2 CTA/SM, __expf)
// ============================================================================
#define LSTRIDE 772
#define QK_SMEM 114176

__global__ __launch_bounds__(256, 2) void qk_softmax(const float* __restrict__ bias,
                                                  const int*   __restrict__ oidx,
                                                  const unsigned char* __restrict__ pmask,
                                                  const unsigned char* __restrict__ emask,
                                                  const __nv_bfloat16* __restrict__ qh_g,
                                                  const __nv_bfloat16* __restrict__ ql_g,
                                                  const __nv_bfloat16* __restrict__ kh_g,
                                                  const __nv_bfloat16* __restrict__ kl_g)
{
    extern __shared__ char sraw[];
    __nv_bfloat16* sqh = (__nv_bfloat16*)sraw;
    __nv_bfloat16* sql = sqh + 1280;
    __nv_bfloat16* skh = sqh + 2560;
    __nv_bfloat16* skl = sqh + 5120;
    float* logits = (float*)(sraw + 15360);

    const int tid  = threadIdx.x;
    const int wid  = tid >> 5;
    const int lane = tid & 31;
    const int g    = lane >> 2;
    const int tig  = lane & 3;
    const int bh   = blockIdx.y;
    const int b    = bh >> 5;
    const int h    = bh & 31;
    const int n0   = blockIdx.x << 5;

    if (tid < 128) {
        int r = tid >> 2, c = (tid & 3) << 3;
        size_t off = (size_t)(b * NN + n0 + r) * NE + h * ND + c;
        *(uint4*)(sqh + r * 40 + c) = *(const uint4*)(qh_g + off);
        *(uint4*)(sql + r * 40 + c) = *(const uint4*)(ql_g + off);
    }

    const int wn = (wid & 1) << 4;
    const int wm = (wid >> 1) << 4;

    for (int m0 = 0; m0 < NEXT; m0 += 64) {
        __syncthreads();
        {
            int r = tid >> 2, c = (tid & 3) << 3;
            int m = m0 + r;
            int row = (m < NN) ? m : oidx[b * NM + m - NN];
            size_t off = (size_t)(b * NN + row) * NE + h * ND + c;
            *(uint4*)(skh + r * 40 + c) = *(const uint4*)(kh_g + off);
            *(uint4*)(skl + r * 40 + c) = *(const uint4*)(kl_g + off);
        }
        __syncthreads();

        float acc[2][4];
        #pragma unroll
        for (int j = 0; j < 2; j++)
            #pragma unroll
            for (int q = 0; q < 4; q++) acc[j][q] = 0.f;

        #pragma unroll
        for (int kk = 0; kk < 2; kk++) {
            const int kw = kk << 3;
            uint32_t a_h[4], a_l[4], bhf[2][2], blf[2][2];
            {
                int rA = wn + g;
                a_h[0] = *(const uint32_t*)(sqh + (rA    ) * 40 + ((kw + tig    ) << 1));
                a_h[1] = *(const uint32_t*)(sqh + (rA + 8) * 40 + ((kw + tig    ) << 1));
                a_h[2] = *(const uint32_t*)(sqh + (rA    ) * 40 + ((kw + tig + 4) << 1));
                a_h[3] = *(const uint32_t*)(sqh + (rA + 8) * 40 + ((kw + tig + 4) << 1));
                a_l[0] = *(const uint32_t*)(sql + (rA    ) * 40 + ((kw + tig    ) << 1));
                a_l[1] = *(const uint32_t*)(sql + (rA + 8) * 40 + ((kw + tig    ) << 1));
                a_l[2] = *(const uint32_t*)(sql + (rA    ) * 40 + ((kw + tig + 4) << 1));
                a_l[3] = *(const uint32_t*)(sql + (rA + 8) * 40 + ((kw + tig + 4) << 1));
            }
            #pragma unroll
            for (int j = 0; j < 2; j++) {
                int rB = wm + (j << 3) + g;
                bhf[j][0] = *(const uint32_t*)(skh + rB * 40 + ((kw + tig    ) << 1));
                bhf[j][1] = *(const uint32_t*)(skh + rB * 40 + ((kw + tig + 4) << 1));
                blf[j][0] = *(const uint32_t*)(skl + rB * 40 + ((kw + tig    ) << 1));
                blf[j][1] = *(const uint32_t*)(skl + rB * 40 + ((kw + tig + 4) << 1));
            }
            #pragma unroll
            for (int j = 0; j < 2; j++) mma16816(acc[j], a_h, bhf[j]);
            #pragma unroll
            for (int j = 0; j < 2; j++) mma16816(acc[j], a_h, blf[j]);
            #pragma unroll
            for (int j = 0; j < 2; j++) mma16816(acc[j], a_l, bhf[j]);
        }

        #pragma unroll
        for (int j = 0; j < 2; j++) {
            int col = m0 + wm + (j << 3) + (tig << 1);
            int row = wn + g;
            *(float2*)&logits[row * LSTRIDE + col]       = make_float2(acc[j][0], acc[j][1]);
            *(float2*)&logits[(row + 8) * LSTRIDE + col] = make_float2(acc[j][2], acc[j][3]);
        }
    }
    __syncthreads();

    for (int rr = wid; rr < 32; rr += 8) {
        int n = n0 + rr;
        bool pn = pmask[b * NN + n] != 0;
        const float* lrow = logits + rr * LSTRIDE;
        long long goff = (((long long)(b * NH + h)) * NN + n) * NEXT;

        float val[24];
        float mx = -FLT_MAX;
        #pragma unroll
        for (int t = 0; t < 24; t++) {
            int m = lane + (t << 5);
            bool fm = (m < NN) ? (pmask[b * NN + m] != 0)
                               : (emask[b * NM + m - NN] != 0);
            float v = lrow[m] + bias[goff + m];
            if (pn || fm) v = -FLT_MAX;
            val[t] = v;
            mx = fmaxf(mx, v);
        }
        #pragma unroll
        for (int o = 16; o > 0; o >>= 1)
            mx = fmaxf(mx, __shfl_xor_sync(0xffffffffu, mx, o));
        float s = 0.f;
        #pragma unroll
        for (int t = 0; t < 24; t++) {
            val[t] = __expf(val[t] - mx);
            s += val[t];
        }
        #pragma unroll
        for (int o = 16; o > 0; o >>= 1)
            s += __shfl_xor_sync(0xffffffffu, s, o);
        float inv = 1.f / s;
        #pragma unroll
        for (int t = 0; t < 24; t++)
            g_attn[goff + lane + (t << 5)] = val[t] * inv;
    }
}

// ============================================================================
// Fused PV + vec, 64-row tile. B mats stored natural [m][d] (stride 40),
// loaded via ldmatrix.trans; A-mat writes vectorized (STS.128).
// smem: A mats 8 x (64x72) = 36864 ele; B mats 4 x (64x40) = 10240 ele.
// ============================================================================
#define PV_A    4608         // 64*72
#define PV_VB   36864        // 8*PV_A
#define PV_BT   2560         // 64*40 (one [m][d] mat)
#define PV_SMEM 94208        // (36864 + 10240) * 2

__global__ __launch_bounds__(256, 2) void pv_mma(const float* __restrict__ delta,
                                                 const int*   __restrict__ oidx,
                                                 const __nv_bfloat16* __restrict__ vh_g,
                                                 const __nv_bfloat16* __restrict__ vl_g,
                                                 const __nv_bfloat16* __restrict__ veh_g,
                                                 const __nv_bfloat16* __restrict__ vel_g,
                                                 __nv_bfloat16* __restrict__ outh,
                                                 __nv_bfloat16* __restrict__ outl)
{
    extern __shared__ __nv_bfloat16 sp[];

    const int tid  = threadIdx.x;
    const int wid  = tid >> 5;
    const int lane = tid & 31;
    const int g    = lane >> 2;
    const int tig  = lane & 3;
    const int b    = blockIdx.z;
    const int h    = blockIdx.y;
    const int n0   = blockIdx.x << 6;

    const int rowblk = (wid & 3) << 4;
    const int pair   = wid >> 2;

    const uint32_t spb = smem_u32(sp);
    const uint32_t a_offp = ((rowblk + (lane & 7) + (((lane >> 3) & 1) << 3)) * 72
                             + ((lane >> 4) << 3)) * 2;
    // trans-B lane offset: row m = (lane&7) + 8*((lane>>3)&1), col d = 8*(lane>>4)
    const uint32_t bt_off = (((lane & 7) + (((lane >> 3) & 1) << 3)) * 40
                             + ((lane >> 4) << 3)) * 2;
    const uint32_t A0u = spb + (((pair == 0) ? 0 : 4) * PV_A) * 2 + a_offp;
    const uint32_t A1u = spb + (((pair == 0) ? 2 : 6) * PV_A) * 2 + a_offp;
    const uint32_t Bvb = spb + PV_VB * 2;
    const uint32_t B0u = ((pair == 0) ? Bvb : Bvb + 2 * PV_BT * 2) + bt_off;
    const uint32_t B1u = Bvb + 2 * PV_BT * 2 + bt_off;

    float acc0[4][4], acc1[4][4];
    #pragma unroll
    for (int j = 0; j < 4; j++)
        #pragma unroll
        for (int q = 0; q < 4; q++) { acc0[j][q] = 0.f; acc1[j][q] = 0.f; }

    const int p_n  = tid >> 2;
    const int p_mb = (tid & 3) << 4;
    const size_t drow = ((size_t)(b * NN + n0 + p_n) * 3) * NEXT;

    for (int m0 = 0; m0 < NEXT; m0 += 64) {
        __syncthreads();
        // ---- phase 1a: P * delta -> 4 scaled A mats (hi/lo), STS.128 ----
        {
            const float* prow = g_attn +
                (((long long)(b * NH + h)) * NN + n0 + p_n) * NEXT + m0 + p_mb;
            #pragma unroll
            for (int half = 0; half < 2; half++) {
                const int ho = half << 3;
                float4 Pa  = *(const float4*)(prow + ho);
                float4 Pb  = *(const float4*)(prow + ho + 4);
                float4 dxa = *(const float4*)(delta + drow            + m0 + p_mb + ho);
                float4 dxb = *(const float4*)(delta + drow            + m0 + p_mb + ho + 4);
                float4 dya = *(const float4*)(delta + drow +     NEXT + m0 + p_mb + ho);
                float4 dyb = *(const float4*)(delta + drow +     NEXT + m0 + p_mb + ho + 4);
                float4 dza = *(const float4*)(delta + drow + 2 * NEXT + m0 + p_mb + ho);
                float4 dzb = *(const float4*)(delta + drow + 2 * NEXT + m0 + p_mb + ho + 4);
                int base = p_n * 72 + p_mb + ho;
                uint4 vh, vl;
                split2(Pa.x, Pa.y, vh.x, vl.x);
                split2(Pa.z, Pa.w, vh.y, vl.y);
                split2(Pb.x, Pb.y, vh.z, vl.z);
                split2(Pb.z, Pb.w, vh.w, vl.w);
                *(uint4*)(sp + 0 * PV_A + base) = vh;
                *(uint4*)(sp + 1 * PV_A + base) = vl;
                split2(Pa.x * dxa.x, Pa.y * dxa.y, vh.x, vl.x);
                split2(Pa.z * dxa.z, Pa.w * dxa.w, vh.y, vl.y);
                split2(Pb.x * dxb.x, Pb.y * dxb.y, vh.z, vl.z);
                split2(Pb.z * dxb.z, Pb.w * dxb.w, vh.w, vl.w);
                *(uint4*)(sp + 2 * PV_A + base) = vh;
                *(uint4*)(sp + 3 * PV_A + base) = vl;
                split2(Pa.x * dya.x, Pa.y * dya.y, vh.x, vl.x);
                split2(Pa.z * dya.z, Pa.w * dya.w, vh.y, vl.y);
                split2(Pb.x * dyb.x, Pb.y * dyb.y, vh.z, vl.z);
                split2(Pb.z * dyb.z, Pb.w * dyb.w, vh.w, vl.w);
                *(uint4*)(sp + 4 * PV_A + base) = vh;
                *(uint4*)(sp + 5 * PV_A + base) = vl;
                split2(Pa.x * dza.x, Pa.y * dza.y, vh.x, vl.x);
                split2(Pa.z * dza.z, Pa.w * dza.w, vh.y, vl.y);
                split2(Pb.x * dzb.x, Pb.y * dzb.y, vh.z, vl.z);
                split2(Pb.z * dzb.z, Pb.w * dzb.w, vh.w, vl.w);
                *(uint4*)(sp + 6 * PV_A + base) = vh;
                *(uint4*)(sp + 7 * PV_A + base) = vl;
            }
        }
        // ---- phase 1b: v / ve tiles in natural [m][d] layout, STS.128 ----
        {
            #pragma unroll
            for (int t = 0; t < 4; t++) {
                int u    = tid + (t << 8);
                int m    = u & 63;
                int rest = u >> 6;
                int dq   = rest & 3;
                int mat  = rest >> 2;   // 0=VEh 1=VEl 2=Vh 3=Vl
                int mg   = m0 + m;
                int row  = (mg < NN) ? mg : oidx[b * NM + mg - NN];
                const __nv_bfloat16* gsrc = (mat == 0) ? veh_g
                                          : (mat == 1) ? vel_g
                                          : (mat == 2) ? vh_g : vl_g;
                uint4 v = *(const uint4*)(gsrc + (size_t)(b * NN + row) * NE
                                          + h * ND + (dq << 3));
                *(uint4*)(sp + PV_VB + mat * PV_BT + m * 40 + (dq << 3)) = v;
            }
        }
        __syncthreads();

        // ---- phase 2: MMAs (A via ldmatrix, B via ldmatrix.trans) ----
        #pragma unroll
        for (int o = 0; o < 2; o++) {
            const uint32_t Au  = o ? A1u : A0u;
            const uint32_t Buo = o ? B1u : B0u;
            float (*acc)[4] = o ? acc1 : acc0;
            #pragma unroll
            for (int kk = 0; kk < 4; kk++) {
                const uint32_t kwb  = kk << 5;       // A: k step 16 ele = 32 B
                const uint32_t bkof = kk * 1280;     // B: 16 rows * 40 ele * 2 B
                uint32_t ah[4], al[4], bh[4][2], bl[4][2];
                ldsm4(ah[0], ah[1], ah[2], ah[3], Au + kwb);
                ldsm4(al[0], al[1], al[2], al[3], Au + PV_A * 2 + kwb);
                // trans loads: each covers two d-tiles (16 d = 32 B apart)
                ldsm4t(bh[0][0], bh[0][1], bh[1][0], bh[1][1], Buo + bkof);
                ldsm4t(bh[2][0], bh[2][1], bh[3][0], bh[3][1], Buo + bkof + 32);
                ldsm4t(bl[0][0], bl[0][1], bl[1][0], bl[1][1], Buo + PV_BT * 2 + bkof);
                ldsm4t(bl[2][0], bl[2][1], bl[3][0], bl[3][1], Buo + PV_BT * 2 + bkof + 32);
                #pragma unroll
                for (int j = 0; j < 4; j++) mma16816(acc[j], ah, bh[j]);
                #pragma unroll
                for (int j = 0; j < 4; j++) mma16816(acc[j], ah, bl[j]);
                #pragma unroll
                for (int j = 0; j < 4; j++) mma16816(acc[j], al, bh[j]);
            }
        }
    }

    // ---- epilogue ----
    const int r0g = n0 + rowblk + g;
    #pragma unroll
    for (int j = 0; j < 4; j++) {
        int col = h * ND + (j << 3) + (tig << 1);
        uint32_t hi, lo;
        if (pair == 0) {
            size_t ro0 = (size_t)(b * NN + r0g) * NE + col;
            size_t ro1 = (size_t)(b * NN + r0g + 8) * NE + col;
            split2(acc0[j][0], acc0[j][1], hi, lo);
            *(uint32_t*)(outh + ro0) = hi; *(uint32_t*)(outl + ro0) = lo;
            split2(acc0[j][2], acc0[j][3], hi, lo);
            *(uint32_t*)(outh + ro1) = hi; *(uint32_t*)(outl + ro1) = lo;
            size_t vo0 = VOFF + ((size_t)(b * NN + r0g) * 3 + 0) * NE + col;
            size_t vo1 = VOFF + ((size_t)(b * NN + r0g + 8) * 3 + 0) * NE + col;
            split2(acc1[j][0], acc1[j][1], hi, lo);
            *(uint32_t*)(outh + vo0) = hi; *(uint32_t*)(outl + vo0) = lo;
            split2(acc1[j][2], acc1[j][3], hi, lo);
            *(uint32_t*)(outh + vo1) = hi; *(uint32_t*)(outl + vo1) = lo;
        } else {
            size_t vo0 = VOFF + ((size_t)(b * NN + r0g) * 3 + 1) * NE + col;
            size_t vo1 = VOFF + ((size_t)(b * NN + r0g + 8) * 3 + 1) * NE + col;
            split2(acc0[j][0], acc0[j][1], hi, lo);
            *(uint32_t*)(outh + vo0) = hi; *(uint32_t*)(outl + vo0) = lo;
            split2(acc0[j][2], acc0[j][3], hi, lo);
            *(uint32_t*)(outh + vo1) = hi; *(uint32_t*)(outl + vo1) = lo;
            size_t wo0 = VOFF + ((size_t)(b * NN + r0g) * 3 + 2) * NE + col;
            size_t wo1 = VOFF + ((size_t)(b * NN + r0g + 8) * 3 + 2) * NE + col;
            split2(acc1[j][0], acc1[j][1], hi, lo);
            *(uint32_t*)(outh + wo0) = hi; *(uint32_t*)(outl + wo0) = lo;
            split2(acc1[j][2], acc1[j][3], hi, lo);
            *(uint32_t*)(outh + wo1) = hi; *(uint32_t*)(outl + wo1) = lo;
        }
    }
}

// ============================================================================
// launch
// ============================================================================
extern "C" void kernel_launch(void* const* d_in, const int* in_sizes, int n_in,
                              void* d_out, int out_size)
{
    const float* x    = (const float*)d_in[0];
    const float* pos  = (const float*)d_in[1];
    const float* epos = (const float*)d_in[2];
    const float* bias = (const float*)d_in[3];
    const unsigned char* pmask = (const unsigned char*)d_in[4];
    const unsigned char* emask = (const unsigned char*)d_in[5];
    const int*   oidx = (const int*)d_in[6];
    const float* Wq   = (const float*)d_in[7];
    const float* Wk   = (const float*)d_in[8];
    const float* Wv   = (const float*)d_in[9];
    const float* Wve  = (const float*)d_in[10];
    const float* Wo   = (const float*)d_in[11];
    const float* Woe  = (const float*)d_in[12];
    float* out = (float*)d_out;

    __nv_bfloat16 *ah, *al, *wh, *wl, *ph, *pl;
    float *dlt;
    cudaGetSymbolAddress((void**)&ah,  g_ah);
    cudaGetSymbolAddress((void**)&al,  g_al);
    cudaGetSymbolAddress((void**)&wh,  g_wh);
    cudaGetSymbolAddress((void**)&wl,  g_wl);
    cudaGetSymbolAddress((void**)&ph,  g_projh);
    cudaGetSymbolAddress((void**)&pl,  g_projl);
    cudaGetSymbolAddress((void**)&dlt, g_delta);

    cudaFuncSetAttribute(gemm_mma,   cudaFuncAttributeMaxDynamicSharedMemorySize, GSMEM_BYTES);
    cudaFuncSetAttribute(qk_softmax, cudaFuncAttributeMaxDynamicSharedMemorySize, QK_SMEM);
    cudaFuncSetAttribute(pv_mma,     cudaFuncAttributeMaxDynamicSharedMemorySize, PV_SMEM);

    const int WSZ = 1024 * 1024;

    // 1) merged prep
    prep<<<14336, 256>>>(x, Wq, Wk, Wv, Wve, Woe, Wo,
                         pos, epos, pmask, emask,
                         ah, al, wh, wl, dlt);

    // 2) projections -> bf16 hi/lo (mode 1)
    gemm_mma<<<dim3(8, 32, 4), 256, GSMEM_BYTES>>>(ah, al, wh, wl,
                                                   nullptr, nullptr, 1024,
                                                   nullptr, ph, pl, SCALING_F, 1);

    // 3) fused QK + softmax
    qk_softmax<<<dim3(8, 256), 256, QK_SMEM>>>(bias, oidx, pmask, emask,
                                               ph, pl, ph + PSZ, pl + PSZ);

    // 4) fused PV + vec
    pv_mma<<<dim3(4, 32, 8), 256, PV_SMEM>>>(dlt, oidx,
                                             ph + 2*PSZ, pl + 2*PSZ,
                                             ph + 3*PSZ, pl + 3*PSZ,
                                             ah, al);

    // 5) fused output GEMMs
    gemm_mma<<<dim3(8, 128, 1), 256, GSMEM_BYTES>>>(ah, al,
                                                    wh + 4*WSZ, wl + 4*WSZ,
                                                    wh + 5*WSZ, wl + 5*WSZ, 32,
                                                    out, nullptr, nullptr, 1.0f, 0);
}

// round 16
// speedup vs baseline: 1.0376x; 1.0109x over previous
#include <cuda_runtime.h>
#include <cuda_bf16.h>
#include <float.h>
#include <math.h>
#include <stdint.h>

// Problem constants
#define NB 8
#define NN 256
#define NM 512
#define NE 1024
#define NH 32
#define ND 32
#define NEXT 768   // N + M

#define SCALING_F 0.17677669529663687f  // 32^-0.5

// ---------------- device scratch ----------------
static __device__ float g_attn[(long long)NB*NH*NN*NEXT];   // probs (fp32)
static __device__ float g_delta[(long long)NB*NN*3*NEXT];   // masked delta [b,n,c,m]
static __device__ __nv_bfloat16 g_ah[8192LL*1024];
static __device__ __nv_bfloat16 g_al[8192LL*1024];
static __device__ __nv_bfloat16 g_wh[6LL*1024*1024];
static __device__ __nv_bfloat16 g_wl[6LL*1024*1024];
static __device__ __nv_bfloat16 g_projh[4LL*2048*1024];
static __device__ __nv_bfloat16 g_projl[4LL*2048*1024];
#define PSZ 2097152
#define VOFF 2097152

// ============================================================================
// helpers
// ============================================================================
__device__ __forceinline__ uint32_t smem_u32(const void* p) {
    uint32_t a;
    asm("{ .reg .u64 t; cvta.to.shared.u64 t, %1; cvt.u32.u64 %0, t; }"
        : "=r"(a) : "l"(p));
    return a;
}
#define CP_ASYNC16(sa, ga) \
    asm volatile("cp.async.cg.shared.global [%0], [%1], 16;\n" :: "r"(sa), "l"(ga))
#define CP_COMMIT() asm volatile("cp.async.commit_group;\n" ::: "memory")
#define CP_WAIT(n)  asm volatile("cp.async.wait_group %0;\n" :: "n"(n) : "memory")

__device__ __forceinline__ void mma16816(float* c, const uint32_t* a, const uint32_t* b) {
    asm volatile(
        "mma.sync.aligned.m16n8k16.row.col.f32.bf16.bf16.f32 "
        "{%0,%1,%2,%3}, {%4,%5,%6,%7}, {%8,%9}, {%0,%1,%2,%3};\n"
        : "+f"(c[0]), "+f"(c[1]), "+f"(c[2]), "+f"(c[3])
        : "r"(a[0]), "r"(a[1]), "r"(a[2]), "r"(a[3]), "r"(b[0]), "r"(b[1]));
}
__device__ __forceinline__ void ldsm4(uint32_t& r0, uint32_t& r1, uint32_t& r2,
                                      uint32_t& r3, uint32_t a) {
    asm volatile("ldmatrix.sync.aligned.m8n8.x4.shared.b16 {%0,%1,%2,%3}, [%4];"
                 : "=r"(r0), "=r"(r1), "=r"(r2), "=r"(r3) : "r"(a));
}
__device__ __forceinline__ void ldsm4t(uint32_t& r0, uint32_t& r1, uint32_t& r2,
                                       uint32_t& r3, uint32_t a) {
    asm volatile("ldmatrix.sync.aligned.m8n8.x4.trans.shared.b16 {%0,%1,%2,%3}, [%4];"
                 : "=r"(r0), "=r"(r1), "=r"(r2), "=r"(r3) : "r"(a));
}
// fast split (bit-identical rn rounding)
__device__ __forceinline__ void split2(float a, float b, uint32_t& hi, uint32_t& lo) {
    asm("cvt.rn.bf16x2.f32 %0, %1, %2;" : "=r"(hi) : "f"(b), "f"(a));
    float ha = __uint_as_float(hi << 16);
    float hb = __uint_as_float(hi & 0xffff0000u);
    asm("cvt.rn.bf16x2.f32 %0, %1, %2;" : "=r"(lo) : "f"(b - hb), "f"(a - ha));
}
__device__ __forceinline__ float sqrt_approx(float x) {
    float r;
    asm("sqrt.approx.f32 %0, %1;" : "=f"(r) : "f"(x));
    return r;
}
__device__ __forceinline__ float rcp_approx(float x) {
    float r;
    asm("rcp.approx.f32 %0, %1;" : "=f"(r) : "f"(x));
    return r;
}

// ============================================================================
// Merged prep: x-convert (0..2047), weight-convert (2048..8191),
// delta precompute (8192..14335).
// ============================================================================
__global__ __launch_bounds__(256) void prep(const float* __restrict__ x,
                                            const float* __restrict__ W0,
                                            const float* __restrict__ W1,
                                            const float* __restrict__ W2,
                                            const float* __restrict__ W3,
                                            const float* __restrict__ W4,
                                            const float* __restrict__ W5,
                                            const float* __restrict__ pos,
                                            const float* __restrict__ epos,
                                            const unsigned char* __restrict__ pmask,
                                            const unsigned char* __restrict__ emask,
                                            __nv_bfloat16* __restrict__ ah,
                                            __nv_bfloat16* __restrict__ al,
                                            __nv_bfloat16* __restrict__ wh,
                                            __nv_bfloat16* __restrict__ wl,
                                            float* __restrict__ delta)
{
    int blk = blockIdx.x;
    if (blk < 2048) {
        int i = blk * 256 + threadIdx.x;
        int r  = i >> 8;
        int e4 = (i & 255) << 2;
        int b = r >> 8, n = r & 255;
        float4 v = *(const float4*)(x + ((long long)n * NB + b) * NE + e4);
        uint32_t h0, l0, h1, l1;
        split2(v.x, v.y, h0, l0);
        split2(v.z, v.w, h1, l1);
        ((uint2*)ah)[i] = make_uint2(h0, h1);
        ((uint2*)al)[i] = make_uint2(l0, l1);
    } else if (blk < 8192) {
        int wsel = (blk - 2048) >> 10;
        const float* src = (wsel == 0) ? W0 : (wsel == 1) ? W1 : (wsel == 2) ? W2
                         : (wsel == 3) ? W3 : (wsel == 4) ? W4 : W5;
        int i = ((blk - 2048) & 1023) * 256 + threadIdx.x;
        float4 v = ((const float4*)src)[i];
        uint32_t h0, l0, h1, l1;
        split2(v.x, v.y, h0, l0);
        split2(v.z, v.w, h1, l1);
        size_t o = ((size_t)wsel << 18) + i;
        ((uint2*)wh)[o] = make_uint2(h0, h1);
        ((uint2*)wl)[o] = make_uint2(l0, l1);
    } else {
        int i = (blk - 8192) * 256 + threadIdx.x;
        int m = i % NEXT;
        int n = (i / NEXT) % NN;
        int b = i / (NEXT * NN);

        float pxn = pos[(b * NN + n) * 3 + 0];
        float pyn = pos[(b * NN + n) * 3 + 1];
        float pzn = pos[(b * NN + n) * 3 + 2];
        bool  pn  = pmask[b * NN + n] != 0;

        float ax, ay, az; bool fm;
        if (m < NN) {
            const float* pp = pos + (b * NN + m) * 3;
            ax = pp[0]; ay = pp[1]; az = pp[2];
            fm = pmask[b * NN + m] != 0;
        } else {
            const float* pp = epos + (b * NM + m - NN) * 3;
            ax = pp[0]; ay = pp[1]; az = pp[2];
            fm = emask[b * NM + m - NN] != 0;
        }
        float dx = pxn - ax, dy = pyn - ay, dz = pzn - az;
        float dist = sqrt_approx(dx * dx + dy * dy + dz * dz);
        if (pn || fm) dist = 1e6f;
        float inv = rcp_approx(dist + 1.f);
        if (pn) inv = 0.f;

        size_t base = ((size_t)(b * NN + n) * 3) * NEXT + m;
        delta[base           ] = dx * inv;
        delta[base +     NEXT] = dy * inv;
        delta[base + 2 * NEXT] = dz * inv;
    }
}

// ============================================================================
// Tensor-core split-precision GEMM, 64x128 CTA tile, 3 CTAs/SM.
// ============================================================================
#define T64_A    2560
#define T64_B    5120
#define STG64    15360
#define GSMEM_BYTES 61440

__global__ __launch_bounds__(256, 3) void gemm_mma(const __nv_bfloat16* __restrict__ Ah,
                                                   const __nv_bfloat16* __restrict__ Al,
                                                   const __nv_bfloat16* __restrict__ Bh,
                                                   const __nv_bfloat16* __restrict__ Bl,
                                                   const __nv_bfloat16* __restrict__ Bh2,
                                                   const __nv_bfloat16* __restrict__ Bl2,
                                                   int ysplit,
                                                   float* __restrict__ C,
                                                   __nv_bfloat16* __restrict__ Ch,
                                                   __nv_bfloat16* __restrict__ Cl,
                                                   float alpha0, int mode)
{
    extern __shared__ __nv_bfloat16 sm[];

    const int tid  = threadIdx.x;
    const int wid  = tid >> 5;
    const int lane = tid & 31;
    const int g    = lane >> 2;
    const int tig  = lane & 3;
    const int row0 = blockIdx.y << 6;
    const int col0 = blockIdx.x << 7;
    const int z    = blockIdx.z;
    if ((int)blockIdx.y >= ysplit) { Bh = Bh2; Bl = Bl2; }
    Bh += (size_t)z << 20;
    Bl += (size_t)z << 20;
    if (mode == 0) C += (size_t)z << 21;
    else { Ch += (size_t)z << 21; Cl += (size_t)z << 21; }
    const float alpha = (z == 0) ? alpha0 : 1.0f;
    const int wm = (wid & 1) << 5;
    const int wn = (wid >> 1) << 5;

    float acc[2][4][4];
    #pragma unroll
    for (int i = 0; i < 2; i++)
        #pragma unroll
        for (int j = 0; j < 4; j++)
            #pragma unroll
            for (int q = 0; q < 4; q++) acc[i][j][q] = 0.f;

    const uint32_t smbase = smem_u32(sm);
    const uint32_t a_off = ((wm + (lane & 7) + (((lane >> 3) & 1) << 3)) * 40
                            + ((lane >> 4) << 3)) * 2;
    const uint32_t b_off = ((wn + (lane & 7) + ((lane >> 4) << 3)) * 40
                            + (((lane >> 3) & 1) << 3)) * 2;

    #define LOAD_CHUNK(kc, s)                                                     \
    {                                                                             \
        _Pragma("unroll")                                                         \
        for (int t = 0; t < 6; t++) {                                             \
            int u  = tid + (t << 8);                                              \
            int r  = u >> 2;                                                      \
            int cu = u & 3;                                                       \
            const __nv_bfloat16* gp;                                              \
            uint32_t selem;                                                       \
            if (r < 64)       { gp = Ah + (size_t)(row0 + r) * 1024;              \
                                selem = r * 40; }                                 \
            else if (r < 128) { gp = Al + (size_t)(row0 + r - 64) * 1024;         \
                                selem = T64_A + (r - 64) * 40; }                  \
            else if (r < 256) { gp = Bh + (size_t)(col0 + r - 128) * 1024;        \
                                selem = 2 * T64_A + (r - 128) * 40; }             \
            else              { gp = Bl + (size_t)(col0 + r - 256) * 1024;        \
                                selem = 2 * T64_A + T64_B + (r - 256) * 40; }     \
            gp += (kc) * 32 + cu * 8;                                             \
            uint32_t sa = smbase + ((s) * STG64 + selem + cu * 8) * 2;            \
            CP_ASYNC16(sa, gp);                                                   \
        }                                                                         \
    }

    LOAD_CHUNK(0, 0);
    CP_COMMIT();

    for (int kc = 0; kc < 32; kc++) {
        CP_WAIT(0);
        __syncthreads();
        if (kc + 1 < 32) {
            LOAD_CHUNK(kc + 1, (kc + 1) & 1);
            CP_COMMIT();
        }

        const uint32_t so2 = (kc & 1) * (STG64 * 2);
        const uint32_t abase = smbase + so2 + a_off;
        const uint32_t bbase = smbase + so2 + 2 * T64_A * 2 + b_off;

        #pragma unroll
        for (int kk = 0; kk < 2; kk++) {
            const uint32_t kwb = kk << 5;
            uint32_t ah[2][4], al[2][4], bh[4][2], bl[4][2];
            #pragma unroll
            for (int i = 0; i < 2; i++) {
                ldsm4(ah[i][0], ah[i][1], ah[i][2], ah[i][3],
                      abase + i * 1280 + kwb);
                ldsm4(al[i][0], al[i][1], al[i][2], al[i][3],
                      abase + T64_A * 2 + i * 1280 + kwb);
            }
            #pragma unroll
            for (int jp = 0; jp < 2; jp++) {
                ldsm4(bh[2*jp][0], bh[2*jp][1], bh[2*jp+1][0], bh[2*jp+1][1],
                      bbase + jp * 1280 + kwb);
                ldsm4(bl[2*jp][0], bl[2*jp][1], bl[2*jp+1][0], bl[2*jp+1][1],
                      bbase + T64_B * 2 + jp * 1280 + kwb);
            }
            #pragma unroll
            for (int i = 0; i < 2; i++)
                #pragma unroll
                for (int j = 0; j < 4; j++)
                    mma16816(acc[i][j], ah[i], bh[j]);
            #pragma unroll
            for (int i = 0; i < 2; i++)
                #pragma unroll
                for (int j = 0; j < 4; j++)
                    mma16816(acc[i][j], ah[i], bl[j]);
            #pragma unroll
            for (int i = 0; i < 2; i++)
                #pragma unroll
                for (int j = 0; j < 4; j++)
                    mma16816(acc[i][j], al[i], bh[j]);
        }
    }

    #pragma unroll
    for (int i = 0; i < 2; i++) {
        int row = row0 + wm + (i << 4) + g;
        #pragma unroll
        for (int j = 0; j < 4; j++) {
            int col = col0 + wn + (j << 3) + (tig << 1);
            float v0 = alpha * acc[i][j][0];
            float v1 = alpha * acc[i][j][1];
            float v2 = alpha * acc[i][j][2];
            float v3 = alpha * acc[i][j][3];
            if (mode == 0) {
                *(float2*)(C + (size_t)row * 1024 + col)       = make_float2(v0, v1);
                *(float2*)(C + (size_t)(row + 8) * 1024 + col) = make_float2(v2, v3);
            } else {
                uint32_t h0, l0, h1, l1;
                split2(v0, v1, h0, l0);
                split2(v2, v3, h1, l1);
                *(uint32_t*)(Ch + (size_t)row * 1024 + col)       = h0;
                *(uint32_t*)(Cl + (size_t)row * 1024 + col)       = l0;
                *(uint32_t*)(Ch + (size_t)(row + 8) * 1024 + col) = h1;
                *(uint32_t*)(Cl + (size_t)(row + 8) * 1024 + col) = l1;
            }
        }
    }
}

// ============================================================================
// Fused QK^T + bias + mask + softmax (32-row tile, 2 CTA/SM, __expf)
// ============================================================================
#define LSTRIDE 772
#define QK_SMEM 114176

__global__ __launch_bounds__(256, 2) void qk_softmax(const float* __restrict__ bias,
                                                  const int*   __restrict__ oidx,
                                                  const unsigned char* __restrict__ pmask,
                                                  const unsigned char* __restrict__ emask,
                                                  const __nv_bfloat16* __restrict__ qh_g,
                                                  const __nv_bfloat16* __restrict__ ql_g,
                                                  const __nv_bfloat16* __restrict__ kh_g,
                                                  const __nv_bfloat16* __restrict__ kl_g)
{
    extern __shared__ char sraw[];
    __nv_bfloat16* sqh = (__nv_bfloat16*)sraw;
    __nv_bfloat16* sql = sqh + 1280;
    __nv_bfloat16* skh = sqh + 2560;
    __nv_bfloat16* skl = sqh + 5120;
    float* logits = (float*)(sraw + 15360);

    const int tid  = threadIdx.x;
    const int wid  = tid >> 5;
    const int lane = tid & 31;
    const int g    = lane >> 2;
    const int tig  = lane & 3;
    const int bh   = blockIdx.y;
    const int b    = bh >> 5;
    const int h    = bh & 31;
    const int n0   = blockIdx.x << 5;

    if (tid < 128) {
        int r = tid >> 2, c = (tid & 3) << 3;
        size_t off = (size_t)(b * NN + n0 + r) * NE + h * ND + c;
        *(uint4*)(sqh + r * 40 + c) = *(const uint4*)(qh_g + off);
        *(uint4*)(sql + r * 40 + c) = *(const uint4*)(ql_g + off);
    }

    const int wn = (wid & 1) << 4;
    const int wm = (wid >> 1) << 4;

    for (int m0 = 0; m0 < NEXT; m0 += 64) {
        __syncthreads();
        {
            int r = tid >> 2, c = (tid & 3) << 3;
            int m = m0 + r;
            int row = (m < NN) ? m : oidx[b * NM + m - NN];
            size_t off = (size_t)(b * NN + row) * NE + h * ND + c;
            *(uint4*)(skh + r * 40 + c) = *(const uint4*)(kh_g + off);
            *(uint4*)(skl + r * 40 + c) = *(const uint4*)(kl_g + off);
        }
        __syncthreads();

        float acc[2][4];
        #pragma unroll
        for (int j = 0; j < 2; j++)
            #pragma unroll
            for (int q = 0; q < 4; q++) acc[j][q] = 0.f;

        #pragma unroll
        for (int kk = 0; kk < 2; kk++) {
            const int kw = kk << 3;
            uint32_t a_h[4], a_l[4], bhf[2][2], blf[2][2];
            {
                int rA = wn + g;
                a_h[0] = *(const uint32_t*)(sqh + (rA    ) * 40 + ((kw + tig    ) << 1));
                a_h[1] = *(const uint32_t*)(sqh + (rA + 8) * 40 + ((kw + tig    ) << 1));
                a_h[2] = *(const uint32_t*)(sqh + (rA    ) * 40 + ((kw + tig + 4) << 1));
                a_h[3] = *(const uint32_t*)(sqh + (rA + 8) * 40 + ((kw + tig + 4) << 1));
                a_l[0] = *(const uint32_t*)(sql + (rA    ) * 40 + ((kw + tig    ) << 1));
                a_l[1] = *(const uint32_t*)(sql + (rA + 8) * 40 + ((kw + tig    ) << 1));
                a_l[2] = *(const uint32_t*)(sql + (rA    ) * 40 + ((kw + tig + 4) << 1));
                a_l[3] = *(const uint32_t*)(sql + (rA + 8) * 40 + ((kw + tig + 4) << 1));
            }
            #pragma unroll
            for (int j = 0; j < 2; j++) {
                int rB = wm + (j << 3) + g;
                bhf[j][0] = *(const uint32_t*)(skh + rB * 40 + ((kw + tig    ) << 1));
                bhf[j][1] = *(const uint32_t*)(skh + rB * 40 + ((kw + tig + 4) << 1));
                blf[j][0] = *(const uint32_t*)(skl + rB * 40 + ((kw + tig    ) << 1));
                blf[j][1] = *(const uint32_t*)(skl + rB * 40 + ((kw + tig + 4) << 1));
            }
            #pragma unroll
            for (int j = 0; j < 2; j++) mma16816(acc[j], a_h, bhf[j]);
            #pragma unroll
            for (int j = 0; j < 2; j++) mma16816(acc[j], a_h, blf[j]);
            #pragma unroll
            for (int j = 0; j < 2; j++) mma16816(acc[j], a_l, bhf[j]);
        }

        #pragma unroll
        for (int j = 0; j < 2; j++) {
            int col = m0 + wm + (j << 3) + (tig << 1);
            int row = wn + g;
            *(float2*)&logits[row * LSTRIDE + col]       = make_float2(acc[j][0], acc[j][1]);
            *(float2*)&logits[(row + 8) * LSTRIDE + col] = make_float2(acc[j][2], acc[j][3]);
        }
    }
    __syncthreads();

    for (int rr = wid; rr < 32; rr += 8) {
        int n = n0 + rr;
        bool pn = pmask[b * NN + n] != 0;
        const float* lrow = logits + rr * LSTRIDE;
        long long goff = (((long long)(b * NH + h)) * NN + n) * NEXT;

        float val[24];
        float mx = -FLT_MAX;
        #pragma unroll
        for (int t = 0; t < 24; t++) {
            int m = lane + (t << 5);
            bool fm = (m < NN) ? (pmask[b * NN + m] != 0)
                               : (emask[b * NM + m - NN] != 0);
            float v = lrow[m] + bias[goff + m];
            if (pn || fm) v = -FLT_MAX;
            val[t] = v;
            mx = fmaxf(mx, v);
        }
        #pragma unroll
        for (int o = 16; o > 0; o >>= 1)
            mx = fmaxf(mx, __shfl_xor_sync(0xffffffffu, mx, o));
        float s = 0.f;
        #pragma unroll
        for (int t = 0; t < 24; t++) {
            val[t] = __expf(val[t] - mx);
            s += val[t];
        }
        #pragma unroll
        for (int o = 16; o > 0; o >>= 1)
            s += __shfl_xor_sync(0xffffffffu, s, o);
        float inv = 1.f / s;
        #pragma unroll
        for (int t = 0; t < 24; t++)
            g_attn[goff + lane + (t << 5)] = val[t] * inv;
    }
}

// ============================================================================
// Fused PV + vec, 64-row tile. A fragments built DIRECTLY IN REGISTERS from
// gmem P/delta (no A smem at all). B mats [m][d] in smem, ldmatrix.trans.
// smem: 4 x (64x40) bf16 = 20480 B.
// Warp roles: rowblk = (wid&3)*16 (A rows), pair = wid>>2:
//   pair 0: acc0 = xo (A=P,    B=VE), acc1 = vx (A=P*dx, B=V)
//   pair 1: acc0 = vy (A=P*dy, B=V),  acc1 = vz (A=P*dz, B=V)
// ============================================================================
#define PV_BT   2560         // 64*40 per B mat
#define PV_SMEM 20480

__global__ __launch_bounds__(256, 2) void pv_mma(const float* __restrict__ attn,
                                                 const float* __restrict__ delta,
                                                 const int*   __restrict__ oidx,
                                                 const __nv_bfloat16* __restrict__ vh_g,
                                                 const __nv_bfloat16* __restrict__ vl_g,
                                                 const __nv_bfloat16* __restrict__ veh_g,
                                                 const __nv_bfloat16* __restrict__ vel_g,
                                                 __nv_bfloat16* __restrict__ outh,
                                                 __nv_bfloat16* __restrict__ outl)
{
    extern __shared__ __nv_bfloat16 sp[];

    const int tid  = threadIdx.x;
    const int wid  = tid >> 5;
    const int lane = tid & 31;
    const int g    = lane >> 2;
    const int tig  = lane & 3;
    const int b    = blockIdx.z;
    const int h    = blockIdx.y;
    const int n0   = blockIdx.x << 6;

    const int rowblk = (wid & 3) << 4;
    const int pair   = wid >> 2;

    const uint32_t spb = smem_u32(sp);
    const uint32_t bt_off = (((lane & 7) + (((lane >> 3) & 1) << 3)) * 40
                             + ((lane >> 4) << 3)) * 2;
    const uint32_t B0u = ((pair == 0) ? spb : spb + 2 * PV_BT * 2) + bt_off;
    const uint32_t B1u = spb + 2 * PV_BT * 2 + bt_off;

    float acc0[4][4], acc1[4][4];
    #pragma unroll
    for (int j = 0; j < 4; j++)
        #pragma unroll
        for (int q = 0; q < 4; q++) { acc0[j][q] = 0.f; acc1[j][q] = 0.f; }

    // A-fragment source row pointers (this warp's two fragment rows)
    const int r0 = n0 + rowblk + g;
    const int r1 = r0 + 8;
    const float* pP0 = attn + ((size_t)(b * NH + h) * NN + r0) * NEXT;
    const float* pP1 = attn + ((size_t)(b * NH + h) * NN + r1) * NEXT;
    const float *pD0r0, *pD0r1, *pD1r0, *pD1r1;
    if (pair == 0) {
        pD0r0 = nullptr; pD0r1 = nullptr;
        pD1r0 = delta + ((size_t)(b * NN + r0) * 3 + 0) * NEXT;
        pD1r1 = delta + ((size_t)(b * NN + r1) * 3 + 0) * NEXT;
    } else {
        pD0r0 = delta + ((size_t)(b * NN + r0) * 3 + 1) * NEXT;
        pD0r1 = delta + ((size_t)(b * NN + r1) * 3 + 1) * NEXT;
        pD1r0 = delta + ((size_t)(b * NN + r0) * 3 + 2) * NEXT;
        pD1r1 = delta + ((size_t)(b * NN + r1) * 3 + 2) * NEXT;
    }

    for (int m0 = 0; m0 < NEXT; m0 += 64) {
        __syncthreads();
        // ---- B gather: v / ve tiles in natural [m][d] layout, STS.128 ----
        {
            #pragma unroll
            for (int t = 0; t < 4; t++) {
                int u    = tid + (t << 8);
                int m    = u & 63;
                int rest = u >> 6;
                int dq   = rest & 3;
                int mat  = rest >> 2;   // 0=VEh 1=VEl 2=Vh 3=Vl
                int mg   = m0 + m;
                int row  = (mg < NN) ? mg : oidx[b * NM + mg - NN];
                const __nv_bfloat16* gsrc = (mat == 0) ? veh_g
                                          : (mat == 1) ? vel_g
                                          : (mat == 2) ? vh_g : vl_g;
                uint4 v = *(const uint4*)(gsrc + (size_t)(b * NN + row) * NE
                                          + h * ND + (dq << 3));
                *(uint4*)(sp + mat * PV_BT + m * 40 + (dq << 3)) = v;
            }
        }
        __syncthreads();

        #pragma unroll
        for (int kk = 0; kk < 4; kk++) {
            const int mm = m0 + (kk << 4) + (tig << 1);
            const uint32_t bkof = kk * 1280;

            // P values for this fragment
            float2 Pa0 = *(const float2*)(pP0 + mm);
            float2 Pb0 = *(const float2*)(pP0 + mm + 8);
            float2 Pa1 = *(const float2*)(pP1 + mm);
            float2 Pb1 = *(const float2*)(pP1 + mm + 8);

            // B fragments for acc0
            uint32_t b0h[4][2], b0l[4][2];
            ldsm4t(b0h[0][0], b0h[0][1], b0h[1][0], b0h[1][1], B0u + bkof);
            ldsm4t(b0h[2][0], b0h[2][1], b0h[3][0], b0h[3][1], B0u + bkof + 32);
            ldsm4t(b0l[0][0], b0l[0][1], b0l[1][0], b0l[1][1], B0u + PV_BT * 2 + bkof);
            ldsm4t(b0l[2][0], b0l[2][1], b0l[3][0], b0l[3][1], B0u + PV_BT * 2 + bkof + 32);

            // A fragment for acc0 (pair0: P; pair1: P*dy)
            uint32_t a0h[4], a0l[4];
            if (pair == 0) {
                split2(Pa0.x, Pa0.y, a0h[0], a0l[0]);
                split2(Pa1.x, Pa1.y, a0h[1], a0l[1]);
                split2(Pb0.x, Pb0.y, a0h[2], a0l[2]);
                split2(Pb1.x, Pb1.y, a0h[3], a0l[3]);
            } else {
                float2 da0 = *(const float2*)(pD0r0 + mm);
                float2 db0 = *(const float2*)(pD0r0 + mm + 8);
                float2 da1 = *(const float2*)(pD0r1 + mm);
                float2 db1 = *(const float2*)(pD0r1 + mm + 8);
                split2(Pa0.x * da0.x, Pa0.y * da0.y, a0h[0], a0l[0]);
                split2(Pa1.x * da1.x, Pa1.y * da1.y, a0h[1], a0l[1]);
                split2(Pb0.x * db0.x, Pb0.y * db0.y, a0h[2], a0l[2]);
                split2(Pb1.x * db1.x, Pb1.y * db1.y, a0h[3], a0l[3]);
            }
            #pragma unroll
            for (int j = 0; j < 4; j++) mma16816(acc0[j], a0h, b0h[j]);
            #pragma unroll
            for (int j = 0; j < 4; j++) mma16816(acc0[j], a0h, b0l[j]);
            #pragma unroll
            for (int j = 0; j < 4; j++) mma16816(acc0[j], a0l, b0h[j]);

            // A fragment for acc1 (pair0: P*dx; pair1: P*dz)
            uint32_t a1h[4], a1l[4];
            {
                float2 da0 = *(const float2*)(pD1r0 + mm);
                float2 db0 = *(const float2*)(pD1r0 + mm + 8);
                float2 da1 = *(const float2*)(pD1r1 + mm);
                float2 db1 = *(const float2*)(pD1r1 + mm + 8);
                split2(Pa0.x * da0.x, Pa0.y * da0.y, a1h[0], a1l[0]);
                split2(Pa1.x * da1.x, Pa1.y * da1.y, a1h[1], a1l[1]);
                split2(Pb0.x * db0.x, Pb0.y * db0.y, a1h[2], a1l[2]);
                split2(Pb1.x * db1.x, Pb1.y * db1.y, a1h[3], a1l[3]);
            }
            if (pair == 0) {
                // acc1 uses B = V (different mats from B0)
                uint32_t b1h[4][2], b1l[4][2];
                ldsm4t(b1h[0][0], b1h[0][1], b1h[1][0], b1h[1][1], B1u + bkof);
                ldsm4t(b1h[2][0], b1h[2][1], b1h[3][0], b1h[3][1], B1u + bkof + 32);
                ldsm4t(b1l[0][0], b1l[0][1], b1l[1][0], b1l[1][1], B1u + PV_BT * 2 + bkof);
                ldsm4t(b1l[2][0], b1l[2][1], b1l[3][0], b1l[3][1], B1u + PV_BT * 2 + bkof + 32);
                #pragma unroll
                for (int j = 0; j < 4; j++) mma16816(acc1[j], a1h, b1h[j]);
                #pragma unroll
                for (int j = 0; j < 4; j++) mma16816(acc1[j], a1h, b1l[j]);
                #pragma unroll
                for (int j = 0; j < 4; j++) mma16816(acc1[j], a1l, b1h[j]);
            } else {
                // acc1 uses the same B (V) already loaded as b0
                #pragma unroll
                for (int j = 0; j < 4; j++) mma16816(acc1[j], a1h, b0h[j]);
                #pragma unroll
                for (int j = 0; j < 4; j++) mma16816(acc1[j], a1h, b0l[j]);
                #pragma unroll
                for (int j = 0; j < 4; j++) mma16816(acc1[j], a1l, b0h[j]);
            }
        }
    }

    // ---- epilogue ----
    const int r0g = n0 + rowblk + g;
    #pragma unroll
    for (int j = 0; j < 4; j++) {
        int col = h * ND + (j << 3) + (tig << 1);
        uint32_t hi, lo;
        if (pair == 0) {
            size_t ro0 = (size_t)(b * NN + r0g) * NE + col;
            size_t ro1 = (size_t)(b * NN + r0g + 8) * NE + col;
            split2(acc0[j][0], acc0[j][1], hi, lo);
            *(uint32_t*)(outh + ro0) = hi; *(uint32_t*)(outl + ro0) = lo;
            split2(acc0[j][2], acc0[j][3], hi, lo);
            *(uint32_t*)(outh + ro1) = hi; *(uint32_t*)(outl + ro1) = lo;
            size_t vo0 = VOFF + ((size_t)(b * NN + r0g) * 3 + 0) * NE + col;
            size_t vo1 = VOFF + ((size_t)(b * NN + r0g + 8) * 3 + 0) * NE + col;
            split2(acc1[j][0], acc1[j][1], hi, lo);
            *(uint32_t*)(outh + vo0) = hi; *(uint32_t*)(outl + vo0) = lo;
            split2(acc1[j][2], acc1[j][3], hi, lo);
            *(uint32_t*)(outh + vo1) = hi; *(uint32_t*)(outl + vo1) = lo;
        } else {
            size_t vo0 = VOFF + ((size_t)(b * NN + r0g) * 3 + 1) * NE + col;
            size_t vo1 = VOFF + ((size_t)(b * NN + r0g + 8) * 3 + 1) * NE + col;
            split2(acc0[j][0], acc0[j][1], hi, lo);
            *(uint32_t*)(outh + vo0) = hi; *(uint32_t*)(outl + vo0) = lo;
            split2(acc0[j][2], acc0[j][3], hi, lo);
            *(uint32_t*)(outh + vo1) = hi; *(uint32_t*)(outl + vo1) = lo;
            size_t wo0 = VOFF + ((size_t)(b * NN + r0g) * 3 + 2) * NE + col;
            size_t wo1 = VOFF + ((size_t)(b * NN + r0g + 8) * 3 + 2) * NE + col;
            split2(acc1[j][0], acc1[j][1], hi, lo);
            *(uint32_t*)(outh + wo0) = hi; *(uint32_t*)(outl + wo0) = lo;
            split2(acc1[j][2], acc1[j][3], hi, lo);
            *(uint32_t*)(outh + wo1) = hi; *(uint32_t*)(outl + wo1) = lo;
        }
    }
}

// ============================================================================
// launch
// ============================================================================
extern "C" void kernel_launch(void* const* d_in, const int* in_sizes, int n_in,
                              void* d_out, int out_size)
{
    const float* x    = (const float*)d_in[0];
    const float* pos  = (const float*)d_in[1];
    const float* epos = (const float*)d_in[2];
    const float* bias = (const float*)d_in[3];
    const unsigned char* pmask = (const unsigned char*)d_in[4];
    const unsigned char* emask = (const unsigned char*)d_in[5];
    const int*   oidx = (const int*)d_in[6];
    const float* Wq   = (const float*)d_in[7];
    const float* Wk   = (const float*)d_in[8];
    const float* Wv   = (const float*)d_in[9];
    const float* Wve  = (const float*)d_in[10];
    const float* Wo   = (const float*)d_in[11];
    const float* Woe  = (const float*)d_in[12];
    float* out = (float*)d_out;

    __nv_bfloat16 *ah, *al, *wh, *wl, *ph, *pl;
    float *dlt, *att;
    cudaGetSymbolAddress((void**)&ah,  g_ah);
    cudaGetSymbolAddress((void**)&al,  g_al);
    cudaGetSymbolAddress((void**)&wh,  g_wh);
    cudaGetSymbolAddress((void**)&wl,  g_wl);
    cudaGetSymbolAddress((void**)&ph,  g_projh);
    cudaGetSymbolAddress((void**)&pl,  g_projl);
    cudaGetSymbolAddress((void**)&dlt, g_delta);
    cudaGetSymbolAddress((void**)&att, g_attn);

    cudaFuncSetAttribute(gemm_mma,   cudaFuncAttributeMaxDynamicSharedMemorySize, GSMEM_BYTES);
    cudaFuncSetAttribute(qk_softmax, cudaFuncAttributeMaxDynamicSharedMemorySize, QK_SMEM);
    cudaFuncSetAttribute(pv_mma,     cudaFuncAttributeMaxDynamicSharedMemorySize, PV_SMEM);

    const int WSZ = 1024 * 1024;

    // 1) merged prep
    prep<<<14336, 256>>>(x, Wq, Wk, Wv, Wve, Woe, Wo,
                         pos, epos, pmask, emask,
                         ah, al, wh, wl, dlt);

    // 2) projections -> bf16 hi/lo (mode 1)
    gemm_mma<<<dim3(8, 32, 4), 256, GSMEM_BYTES>>>(ah, al, wh, wl,
                                                   nullptr, nullptr, 1024,
                                                   nullptr, ph, pl, SCALING_F, 1);

    // 3) fused QK + softmax
    qk_softmax<<<dim3(8, 256), 256, QK_SMEM>>>(bias, oidx, pmask, emask,
                                               ph, pl, ph + PSZ, pl + PSZ);

    // 4) fused PV + vec (register-built A fragments)
    pv_mma<<<dim3(4, 32, 8), 256, PV_SMEM>>>(att, dlt, oidx,
                                             ph + 2*PSZ, pl + 2*PSZ,
                                             ph + 3*PSZ, pl + 3*PSZ,
                                             ah, al);

    // 5) fused output GEMMs
    gemm_mma<<<dim3(8, 128, 1), 256, GSMEM_BYTES>>>(ah, al,
                                                    wh + 4*WSZ, wl + 4*WSZ,
                                                    wh + 5*WSZ, wl + 5*WSZ, 32,
                                                    out, nullptr, nullptr, 1.0f, 0);
}

// round 17
// speedup vs baseline: 1.0439x; 1.0060x over previous
#include <cuda_runtime.h>
#include <cuda_bf16.h>
#include <float.h>
#include <math.h>
#include <stdint.h>

// Problem constants
#define NB 8
#define NN 256
#define NM 512
#define NE 1024
#define NH 32
#define ND 32
#define NEXT 768   // N + M

#define SCALING_F 0.17677669529663687f  // 32^-0.5

// ---------------- device scratch ----------------
static __device__ float g_attn[(long long)NB*NH*NN*NEXT];   // probs (fp32)
static __device__ float g_delta[(long long)NB*NN*3*NEXT];   // masked delta [b,n,c,m]
static __device__ __nv_bfloat16 g_ah[8192LL*1024];
static __device__ __nv_bfloat16 g_al[8192LL*1024];
static __device__ __nv_bfloat16 g_wh[6LL*1024*1024];
static __device__ __nv_bfloat16 g_wl[6LL*1024*1024];
static __device__ __nv_bfloat16 g_projh[4LL*2048*1024];
static __device__ __nv_bfloat16 g_projl[4LL*2048*1024];
#define PSZ 2097152
#define VOFF 2097152

// ============================================================================
// helpers
// ============================================================================
__device__ __forceinline__ uint32_t smem_u32(const void* p) {
    uint32_t a;
    asm("{ .reg .u64 t; cvta.to.shared.u64 t, %1; cvt.u32.u64 %0, t; }"
        : "=r"(a) : "l"(p));
    return a;
}
#define CP_ASYNC16(sa, ga) \
    asm volatile("cp.async.cg.shared.global [%0], [%1], 16;\n" :: "r"(sa), "l"(ga))
#define CP_COMMIT() asm volatile("cp.async.commit_group;\n" ::: "memory")
#define CP_WAIT(n)  asm volatile("cp.async.wait_group %0;\n" :: "n"(n) : "memory")

__device__ __forceinline__ void mma16816(float* c, const uint32_t* a, const uint32_t* b) {
    asm volatile(
        "mma.sync.aligned.m16n8k16.row.col.f32.bf16.bf16.f32 "
        "{%0,%1,%2,%3}, {%4,%5,%6,%7}, {%8,%9}, {%0,%1,%2,%3};\n"
        : "+f"(c[0]), "+f"(c[1]), "+f"(c[2]), "+f"(c[3])
        : "r"(a[0]), "r"(a[1]), "r"(a[2]), "r"(a[3]), "r"(b[0]), "r"(b[1]));
}
__device__ __forceinline__ void ldsm4(uint32_t& r0, uint32_t& r1, uint32_t& r2,
                                      uint32_t& r3, uint32_t a) {
    asm volatile("ldmatrix.sync.aligned.m8n8.x4.shared.b16 {%0,%1,%2,%3}, [%4];"
                 : "=r"(r0), "=r"(r1), "=r"(r2), "=r"(r3) : "r"(a));
}
__device__ __forceinline__ void ldsm4t(uint32_t& r0, uint32_t& r1, uint32_t& r2,
                                       uint32_t& r3, uint32_t a) {
    asm volatile("ldmatrix.sync.aligned.m8n8.x4.trans.shared.b16 {%0,%1,%2,%3}, [%4];"
                 : "=r"(r0), "=r"(r1), "=r"(r2), "=r"(r3) : "r"(a));
}
// fast split (bit-identical rn rounding)
__device__ __forceinline__ void split2(float a, float b, uint32_t& hi, uint32_t& lo) {
    asm("cvt.rn.bf16x2.f32 %0, %1, %2;" : "=r"(hi) : "f"(b), "f"(a));
    float ha = __uint_as_float(hi << 16);
    float hb = __uint_as_float(hi & 0xffff0000u);
    asm("cvt.rn.bf16x2.f32 %0, %1, %2;" : "=r"(lo) : "f"(b - hb), "f"(a - ha));
}
__device__ __forceinline__ float sqrt_approx(float x) {
    float r;
    asm("sqrt.approx.f32 %0, %1;" : "=f"(r) : "f"(x));
    return r;
}
__device__ __forceinline__ float rcp_approx(float x) {
    float r;
    asm("rcp.approx.f32 %0, %1;" : "=f"(r) : "f"(x));
    return r;
}

// ============================================================================
// Merged prep: x-convert (0..2047), weight-convert (2048..8191),
// delta precompute (8192..14335).
// ============================================================================
__global__ __launch_bounds__(256) void prep(const float* __restrict__ x,
                                            const float* __restrict__ W0,
                                            const float* __restrict__ W1,
                                            const float* __restrict__ W2,
                                            const float* __restrict__ W3,
                                            const float* __restrict__ W4,
                                            const float* __restrict__ W5,
                                            const float* __restrict__ pos,
                                            const float* __restrict__ epos,
                                            const unsigned char* __restrict__ pmask,
                                            const unsigned char* __restrict__ emask,
                                            __nv_bfloat16* __restrict__ ah,
                                            __nv_bfloat16* __restrict__ al,
                                            __nv_bfloat16* __restrict__ wh,
                                            __nv_bfloat16* __restrict__ wl,
                                            float* __restrict__ delta)
{
    int blk = blockIdx.x;
    if (blk < 2048) {
        int i = blk * 256 + threadIdx.x;
        int r  = i >> 8;
        int e4 = (i & 255) << 2;
        int b = r >> 8, n = r & 255;
        float4 v = *(const float4*)(x + ((long long)n * NB + b) * NE + e4);
        uint32_t h0, l0, h1, l1;
        split2(v.x, v.y, h0, l0);
        split2(v.z, v.w, h1, l1);
        ((uint2*)ah)[i] = make_uint2(h0, h1);
        ((uint2*)al)[i] = make_uint2(l0, l1);
    } else if (blk < 8192) {
        int wsel = (blk - 2048) >> 10;
        const float* src = (wsel == 0) ? W0 : (wsel == 1) ? W1 : (wsel == 2) ? W2
                         : (wsel == 3) ? W3 : (wsel == 4) ? W4 : W5;
        int i = ((blk - 2048) & 1023) * 256 + threadIdx.x;
        float4 v = ((const float4*)src)[i];
        uint32_t h0, l0, h1, l1;
        split2(v.x, v.y, h0, l0);
        split2(v.z, v.w, h1, l1);
        size_t o = ((size_t)wsel << 18) + i;
        ((uint2*)wh)[o] = make_uint2(h0, h1);
        ((uint2*)wl)[o] = make_uint2(l0, l1);
    } else {
        int i = (blk - 8192) * 256 + threadIdx.x;
        int m = i % NEXT;
        int n = (i / NEXT) % NN;
        int b = i / (NEXT * NN);

        float pxn = pos[(b * NN + n) * 3 + 0];
        float pyn = pos[(b * NN + n) * 3 + 1];
        float pzn = pos[(b * NN + n) * 3 + 2];
        bool  pn  = pmask[b * NN + n] != 0;

        float ax, ay, az; bool fm;
        if (m < NN) {
            const float* pp = pos + (b * NN + m) * 3;
            ax = pp[0]; ay = pp[1]; az = pp[2];
            fm = pmask[b * NN + m] != 0;
        } else {
            const float* pp = epos + (b * NM + m - NN) * 3;
            ax = pp[0]; ay = pp[1]; az = pp[2];
            fm = emask[b * NM + m - NN] != 0;
        }
        float dx = pxn - ax, dy = pyn - ay, dz = pzn - az;
        float dist = sqrt_approx(dx * dx + dy * dy + dz * dz);
        if (pn || fm) dist = 1e6f;
        float inv = rcp_approx(dist + 1.f);
        if (pn) inv = 0.f;

        size_t base = ((size_t)(b * NN + n) * 3) * NEXT + m;
        delta[base           ] = dx * inv;
        delta[base +     NEXT] = dy * inv;
        delta[base + 2 * NEXT] = dz * inv;
    }
}

// ============================================================================
// Tensor-core split-precision GEMM, 64x128 CTA tile, 3 CTAs/SM.
// ============================================================================
#define T64_A    2560
#define T64_B    5120
#define STG64    15360
#define GSMEM_BYTES 61440

__global__ __launch_bounds__(256, 3) void gemm_mma(const __nv_bfloat16* __restrict__ Ah,
                                                   const __nv_bfloat16* __restrict__ Al,
                                                   const __nv_bfloat16* __restrict__ Bh,
                                                   const __nv_bfloat16* __restrict__ Bl,
                                                   const __nv_bfloat16* __restrict__ Bh2,
                                                   const __nv_bfloat16* __restrict__ Bl2,
                                                   int ysplit,
                                                   float* __restrict__ C,
                                                   __nv_bfloat16* __restrict__ Ch,
                                                   __nv_bfloat16* __restrict__ Cl,
                                                   float alpha0, int mode)
{
    extern __shared__ __nv_bfloat16 sm[];

    const int tid  = threadIdx.x;
    const int wid  = tid >> 5;
    const int lane = tid & 31;
    const int g    = lane >> 2;
    const int tig  = lane & 3;
    const int row0 = blockIdx.y << 6;
    const int col0 = blockIdx.x << 7;
    const int z    = blockIdx.z;
    if ((int)blockIdx.y >= ysplit) { Bh = Bh2; Bl = Bl2; }
    Bh += (size_t)z << 20;
    Bl += (size_t)z << 20;
    if (mode == 0) C += (size_t)z << 21;
    else { Ch += (size_t)z << 21; Cl += (size_t)z << 21; }
    const float alpha = (z == 0) ? alpha0 : 1.0f;
    const int wm = (wid & 1) << 5;
    const int wn = (wid >> 1) << 5;

    float acc[2][4][4];
    #pragma unroll
    for (int i = 0; i < 2; i++)
        #pragma unroll
        for (int j = 0; j < 4; j++)
            #pragma unroll
            for (int q = 0; q < 4; q++) acc[i][j][q] = 0.f;

    const uint32_t smbase = smem_u32(sm);
    const uint32_t a_off = ((wm + (lane & 7) + (((lane >> 3) & 1) << 3)) * 40
                            + ((lane >> 4) << 3)) * 2;
    const uint32_t b_off = ((wn + (lane & 7) + ((lane >> 4) << 3)) * 40
                            + (((lane >> 3) & 1) << 3)) * 2;

    #define LOAD_CHUNK(kc, s)                                                     \
    {                                                                             \
        _Pragma("unroll")                                                         \
        for (int t = 0; t < 6; t++) {                                             \
            int u  = tid + (t << 8);                                              \
            int r  = u >> 2;                                                      \
            int cu = u & 3;                                                       \
            const __nv_bfloat16* gp;                                              \
            uint32_t selem;                                                       \
            if (r < 64)       { gp = Ah + (size_t)(row0 + r) * 1024;              \
                                selem = r * 40; }                                 \
            else if (r < 128) { gp = Al + (size_t)(row0 + r - 64) * 1024;         \
                                selem = T64_A + (r - 64) * 40; }                  \
            else if (r < 256) { gp = Bh + (size_t)(col0 + r - 128) * 1024;        \
                                selem = 2 * T64_A + (r - 128) * 40; }             \
            else              { gp = Bl + (size_t)(col0 + r - 256) * 1024;        \
                                selem = 2 * T64_A + T64_B + (r - 256) * 40; }     \
            gp += (kc) * 32 + cu * 8;                                             \
            uint32_t sa = smbase + ((s) * STG64 + selem + cu * 8) * 2;            \
            CP_ASYNC16(sa, gp);                                                   \
        }                                                                         \
    }

    LOAD_CHUNK(0, 0);
    CP_COMMIT();

    for (int kc = 0; kc < 32; kc++) {
        CP_WAIT(0);
        __syncthreads();
        if (kc + 1 < 32) {
            LOAD_CHUNK(kc + 1, (kc + 1) & 1);
            CP_COMMIT();
        }

        const uint32_t so2 = (kc & 1) * (STG64 * 2);
        const uint32_t abase = smbase + so2 + a_off;
        const uint32_t bbase = smbase + so2 + 2 * T64_A * 2 + b_off;

        #pragma unroll
        for (int kk = 0; kk < 2; kk++) {
            const uint32_t kwb = kk << 5;
            uint32_t ah[2][4], al[2][4], bh[4][2], bl[4][2];
            #pragma unroll
            for (int i = 0; i < 2; i++) {
                ldsm4(ah[i][0], ah[i][1], ah[i][2], ah[i][3],
                      abase + i * 1280 + kwb);
                ldsm4(al[i][0], al[i][1], al[i][2], al[i][3],
                      abase + T64_A * 2 + i * 1280 + kwb);
            }
            #pragma unroll
            for (int jp = 0; jp < 2; jp++) {
                ldsm4(bh[2*jp][0], bh[2*jp][1], bh[2*jp+1][0], bh[2*jp+1][1],
                      bbase + jp * 1280 + kwb);
                ldsm4(bl[2*jp][0], bl[2*jp][1], bl[2*jp+1][0], bl[2*jp+1][1],
                      bbase + T64_B * 2 + jp * 1280 + kwb);
            }
            #pragma unroll
            for (int i = 0; i < 2; i++)
                #pragma unroll
                for (int j = 0; j < 4; j++)
                    mma16816(acc[i][j], ah[i], bh[j]);
            #pragma unroll
            for (int i = 0; i < 2; i++)
                #pragma unroll
                for (int j = 0; j < 4; j++)
                    mma16816(acc[i][j], ah[i], bl[j]);
            #pragma unroll
            for (int i = 0; i < 2; i++)
                #pragma unroll
                for (int j = 0; j < 4; j++)
                    mma16816(acc[i][j], al[i], bh[j]);
        }
    }

    #pragma unroll
    for (int i = 0; i < 2; i++) {
        int row = row0 + wm + (i << 4) + g;
        #pragma unroll
        for (int j = 0; j < 4; j++) {
            int col = col0 + wn + (j << 3) + (tig << 1);
            float v0 = alpha * acc[i][j][0];
            float v1 = alpha * acc[i][j][1];
            float v2 = alpha * acc[i][j][2];
            float v3 = alpha * acc[i][j][3];
            if (mode == 0) {
                *(float2*)(C + (size_t)row * 1024 + col)       = make_float2(v0, v1);
                *(float2*)(C + (size_t)(row + 8) * 1024 + col) = make_float2(v2, v3);
            } else {
                uint32_t h0, l0, h1, l1;
                split2(v0, v1, h0, l0);
                split2(v2, v3, h1, l1);
                *(uint32_t*)(Ch + (size_t)row * 1024 + col)       = h0;
                *(uint32_t*)(Cl + (size_t)row * 1024 + col)       = l0;
                *(uint32_t*)(Ch + (size_t)(row + 8) * 1024 + col) = h1;
                *(uint32_t*)(Cl + (size_t)(row + 8) * 1024 + col) = l1;
            }
        }
    }
}

// ============================================================================
// Fused QK^T + bias + mask + softmax (32-row tile, 2 CTA/SM, __expf)
// ============================================================================
#define LSTRIDE 772
#define QK_SMEM 114176

__global__ __launch_bounds__(256, 2) void qk_softmax(const float* __restrict__ bias,
                                                  const int*   __restrict__ oidx,
                                                  const unsigned char* __restrict__ pmask,
                                                  const unsigned char* __restrict__ emask,
                                                  const __nv_bfloat16* __restrict__ qh_g,
                                                  const __nv_bfloat16* __restrict__ ql_g,
                                                  const __nv_bfloat16* __restrict__ kh_g,
                                                  const __nv_bfloat16* __restrict__ kl_g)
{
    extern __shared__ char sraw[];
    __nv_bfloat16* sqh = (__nv_bfloat16*)sraw;
    __nv_bfloat16* sql = sqh + 1280;
    __nv_bfloat16* skh = sqh + 2560;
    __nv_bfloat16* skl = sqh + 5120;
    float* logits = (float*)(sraw + 15360);

    const int tid  = threadIdx.x;
    const int wid  = tid >> 5;
    const int lane = tid & 31;
    const int g    = lane >> 2;
    const int tig  = lane & 3;
    const int bh   = blockIdx.y;
    const int b    = bh >> 5;
    const int h    = bh & 31;
    const int n0   = blockIdx.x << 5;

    if (tid < 128) {
        int r = tid >> 2, c = (tid & 3) << 3;
        size_t off = (size_t)(b * NN + n0 + r) * NE + h * ND + c;
        *(uint4*)(sqh + r * 40 + c) = *(const uint4*)(qh_g + off);
        *(uint4*)(sql + r * 40 + c) = *(const uint4*)(ql_g + off);
    }

    const int wn = (wid & 1) << 4;
    const int wm = (wid >> 1) << 4;

    for (int m0 = 0; m0 < NEXT; m0 += 64) {
        __syncthreads();
        {
            int r = tid >> 2, c = (tid & 3) << 3;
            int m = m0 + r;
            int row = (m < NN) ? m : oidx[b * NM + m - NN];
            size_t off = (size_t)(b * NN + row) * NE + h * ND + c;
            *(uint4*)(skh + r * 40 + c) = *(const uint4*)(kh_g + off);
            *(uint4*)(skl + r * 40 + c) = *(const uint4*)(kl_g + off);
        }
        __syncthreads();

        float acc[2][4];
        #pragma unroll
        for (int j = 0; j < 2; j++)
            #pragma unroll
            for (int q = 0; q < 4; q++) acc[j][q] = 0.f;

        #pragma unroll
        for (int kk = 0; kk < 2; kk++) {
            const int kw = kk << 3;
            uint32_t a_h[4], a_l[4], bhf[2][2], blf[2][2];
            {
                int rA = wn + g;
                a_h[0] = *(const uint32_t*)(sqh + (rA    ) * 40 + ((kw + tig    ) << 1));
                a_h[1] = *(const uint32_t*)(sqh + (rA + 8) * 40 + ((kw + tig    ) << 1));
                a_h[2] = *(const uint32_t*)(sqh + (rA    ) * 40 + ((kw + tig + 4) << 1));
                a_h[3] = *(const uint32_t*)(sqh + (rA + 8) * 40 + ((kw + tig + 4) << 1));
                a_l[0] = *(const uint32_t*)(sql + (rA    ) * 40 + ((kw + tig    ) << 1));
                a_l[1] = *(const uint32_t*)(sql + (rA + 8) * 40 + ((kw + tig    ) << 1));
                a_l[2] = *(const uint32_t*)(sql + (rA    ) * 40 + ((kw + tig + 4) << 1));
                a_l[3] = *(const uint32_t*)(sql + (rA + 8) * 40 + ((kw + tig + 4) << 1));
            }
            #pragma unroll
            for (int j = 0; j < 2; j++) {
                int rB = wm + (j << 3) + g;
                bhf[j][0] = *(const uint32_t*)(skh + rB * 40 + ((kw + tig    ) << 1));
                bhf[j][1] = *(const uint32_t*)(skh + rB * 40 + ((kw + tig + 4) << 1));
                blf[j][0] = *(const uint32_t*)(skl + rB * 40 + ((kw + tig    ) << 1));
                blf[j][1] = *(const uint32_t*)(skl + rB * 40 + ((kw + tig + 4) << 1));
            }
            #pragma unroll
            for (int j = 0; j < 2; j++) mma16816(acc[j], a_h, bhf[j]);
            #pragma unroll
            for (int j = 0; j < 2; j++) mma16816(acc[j], a_h, blf[j]);
            #pragma unroll
            for (int j = 0; j < 2; j++) mma16816(acc[j], a_l, bhf[j]);
        }

        #pragma unroll
        for (int j = 0; j < 2; j++) {
            int col = m0 + wm + (j << 3) + (tig << 1);
            int row = wn + g;
            *(float2*)&logits[row * LSTRIDE + col]       = make_float2(acc[j][0], acc[j][1]);
            *(float2*)&logits[(row + 8) * LSTRIDE + col] = make_float2(acc[j][2], acc[j][3]);
        }
    }
    __syncthreads();

    for (int rr = wid; rr < 32; rr += 8) {
        int n = n0 + rr;
        bool pn = pmask[b * NN + n] != 0;
        const float* lrow = logits + rr * LSTRIDE;
        long long goff = (((long long)(b * NH + h)) * NN + n) * NEXT;

        float val[24];
        float mx = -FLT_MAX;
        #pragma unroll
        for (int t = 0; t < 24; t++) {
            int m = lane + (t << 5);
            bool fm = (m < NN) ? (pmask[b * NN + m] != 0)
                               : (emask[b * NM + m - NN] != 0);
            float v = lrow[m] + bias[goff + m];
            if (pn || fm) v = -FLT_MAX;
            val[t] = v;
            mx = fmaxf(mx, v);
        }
        #pragma unroll
        for (int o = 16; o > 0; o >>= 1)
            mx = fmaxf(mx, __shfl_xor_sync(0xffffffffu, mx, o));
        float s = 0.f;
        #pragma unroll
        for (int t = 0; t < 24; t++) {
            val[t] = __expf(val[t] - mx);
            s += val[t];
        }
        #pragma unroll
        for (int o = 16; o > 0; o >>= 1)
            s += __shfl_xor_sync(0xffffffffu, s, o);
        float inv = 1.f / s;
        #pragma unroll
        for (int t = 0; t < 24; t++)
            g_attn[goff + lane + (t << 5)] = val[t] * inv;
    }
}

// ============================================================================
// Fused PV + vec, 64-row tile, register-built A fragments, B gather
// SOFTWARE-PIPELINED (prefetch next tile's gather into regs during MMAs).
// smem: 4 x (64x40) bf16 = 20480 B.
// ============================================================================
#define PV_BT   2560
#define PV_SMEM 20480

__global__ __launch_bounds__(256, 2) void pv_mma(const float* __restrict__ attn,
                                                 const float* __restrict__ delta,
                                                 const int*   __restrict__ oidx,
                                                 const __nv_bfloat16* __restrict__ vh_g,
                                                 const __nv_bfloat16* __restrict__ vl_g,
                                                 const __nv_bfloat16* __restrict__ veh_g,
                                                 const __nv_bfloat16* __restrict__ vel_g,
                                                 __nv_bfloat16* __restrict__ outh,
                                                 __nv_bfloat16* __restrict__ outl)
{
    extern __shared__ __nv_bfloat16 sp[];

    const int tid  = threadIdx.x;
    const int wid  = tid >> 5;
    const int lane = tid & 31;
    const int g    = lane >> 2;
    const int tig  = lane & 3;
    const int b    = blockIdx.z;
    const int h    = blockIdx.y;
    const int n0   = blockIdx.x << 6;

    const int rowblk = (wid & 3) << 4;
    const int pair   = wid >> 2;

    const uint32_t spb = smem_u32(sp);
    const uint32_t bt_off = (((lane & 7) + (((lane >> 3) & 1) << 3)) * 40
                             + ((lane >> 4) << 3)) * 2;
    const uint32_t B0u = ((pair == 0) ? spb : spb + 2 * PV_BT * 2) + bt_off;
    const uint32_t B1u = spb + 2 * PV_BT * 2 + bt_off;

    float acc0[4][4], acc1[4][4];
    #pragma unroll
    for (int j = 0; j < 4; j++)
        #pragma unroll
        for (int q = 0; q < 4; q++) { acc0[j][q] = 0.f; acc1[j][q] = 0.f; }

    const int r0 = n0 + rowblk + g;
    const int r1 = r0 + 8;
    const float* pP0 = attn + ((size_t)(b * NH + h) * NN + r0) * NEXT;
    const float* pP1 = attn + ((size_t)(b * NH + h) * NN + r1) * NEXT;
    const float *pD0r0, *pD0r1, *pD1r0, *pD1r1;
    if (pair == 0) {
        pD0r0 = nullptr; pD0r1 = nullptr;
        pD1r0 = delta + ((size_t)(b * NN + r0) * 3 + 0) * NEXT;
        pD1r1 = delta + ((size_t)(b * NN + r1) * 3 + 0) * NEXT;
    } else {
        pD0r0 = delta + ((size_t)(b * NN + r0) * 3 + 1) * NEXT;
        pD0r1 = delta + ((size_t)(b * NN + r1) * 3 + 1) * NEXT;
        pD1r0 = delta + ((size_t)(b * NN + r0) * 3 + 2) * NEXT;
        pD1r1 = delta + ((size_t)(b * NN + r1) * 3 + 2) * NEXT;
    }

    // per-thread gather geometry (constant across tiles)
    const int gm    = tid & 63;           // m within tile
    const int grest = tid >> 6;
    const int gdq   = grest & 3;          // 8-dim quarter
    // mat index per t: mat = (tid + t*256) >> 8 ... rest>>2 with t folded:
    //   u = tid + t*256 -> rest = u>>6 = grest + t*4 -> mat = rest>>2 = t (since grest<4)
    // so prefetch t reads matrix t: 0=VEh 1=VEl 2=Vh 3=Vl at (m=gm, dq=gdq).

    #define GATHER_LOAD(m0v, pf)                                                  \
    {                                                                             \
        int mg  = (m0v) + gm;                                                     \
        int row = (mg < NN) ? mg : oidx[b * NM + mg - NN];                        \
        size_t goff2 = (size_t)(b * NN + row) * NE + h * ND + (gdq << 3);         \
        pf[0] = *(const uint4*)(veh_g + goff2);                                   \
        pf[1] = *(const uint4*)(vel_g + goff2);                                   \
        pf[2] = *(const uint4*)(vh_g  + goff2);                                   \
        pf[3] = *(const uint4*)(vl_g  + goff2);                                   \
    }

    uint4 pf[4];
    GATHER_LOAD(0, pf);

    for (int m0 = 0; m0 < NEXT; m0 += 64) {
        __syncthreads();   // previous tile's MMA reads complete
        {
            uint32_t sdst = gm * 40 + (gdq << 3);
            *(uint4*)(sp + 0 * PV_BT + sdst) = pf[0];
            *(uint4*)(sp + 1 * PV_BT + sdst) = pf[1];
            *(uint4*)(sp + 2 * PV_BT + sdst) = pf[2];
            *(uint4*)(sp + 3 * PV_BT + sdst) = pf[3];
        }
        __syncthreads();   // stores visible
        if (m0 + 64 < NEXT) GATHER_LOAD(m0 + 64, pf);   // overlap with MMAs

        #pragma unroll
        for (int kk = 0; kk < 4; kk++) {
            const int mm = m0 + (kk << 4) + (tig << 1);
            const uint32_t bkof = kk * 1280;

            float2 Pa0 = *(const float2*)(pP0 + mm);
            float2 Pb0 = *(const float2*)(pP0 + mm + 8);
            float2 Pa1 = *(const float2*)(pP1 + mm);
            float2 Pb1 = *(const float2*)(pP1 + mm + 8);

            uint32_t b0h[4][2], b0l[4][2];
            ldsm4t(b0h[0][0], b0h[0][1], b0h[1][0], b0h[1][1], B0u + bkof);
            ldsm4t(b0h[2][0], b0h[2][1], b0h[3][0], b0h[3][1], B0u + bkof + 32);
            ldsm4t(b0l[0][0], b0l[0][1], b0l[1][0], b0l[1][1], B0u + PV_BT * 2 + bkof);
            ldsm4t(b0l[2][0], b0l[2][1], b0l[3][0], b0l[3][1], B0u + PV_BT * 2 + bkof + 32);

            uint32_t a0h[4], a0l[4];
            if (pair == 0) {
                split2(Pa0.x, Pa0.y, a0h[0], a0l[0]);
                split2(Pa1.x, Pa1.y, a0h[1], a0l[1]);
                split2(Pb0.x, Pb0.y, a0h[2], a0l[2]);
                split2(Pb1.x, Pb1.y, a0h[3], a0l[3]);
            } else {
                float2 da0 = *(const float2*)(pD0r0 + mm);
                float2 db0 = *(const float2*)(pD0r0 + mm + 8);
                float2 da1 = *(const float2*)(pD0r1 + mm);
                float2 db1 = *(const float2*)(pD0r1 + mm + 8);
                split2(Pa0.x * da0.x, Pa0.y * da0.y, a0h[0], a0l[0]);
                split2(Pa1.x * da1.x, Pa1.y * da1.y, a0h[1], a0l[1]);
                split2(Pb0.x * db0.x, Pb0.y * db0.y, a0h[2], a0l[2]);
                split2(Pb1.x * db1.x, Pb1.y * db1.y, a0h[3], a0l[3]);
            }
            #pragma unroll
            for (int j = 0; j < 4; j++) mma16816(acc0[j], a0h, b0h[j]);
            #pragma unroll
            for (int j = 0; j < 4; j++) mma16816(acc0[j], a0h, b0l[j]);
            #pragma unroll
            for (int j = 0; j < 4; j++) mma16816(acc0[j], a0l, b0h[j]);

            uint32_t a1h[4], a1l[4];
            {
                float2 da0 = *(const float2*)(pD1r0 + mm);
                float2 db0 = *(const float2*)(pD1r0 + mm + 8);
                float2 da1 = *(const float2*)(pD1r1 + mm);
                float2 db1 = *(const float2*)(pD1r1 + mm + 8);
                split2(Pa0.x * da0.x, Pa0.y * da0.y, a1h[0], a1l[0]);
                split2(Pa1.x * da1.x, Pa1.y * da1.y, a1h[1], a1l[1]);
                split2(Pb0.x * db0.x, Pb0.y * db0.y, a1h[2], a1l[2]);
                split2(Pb1.x * db1.x, Pb1.y * db1.y, a1h[3], a1l[3]);
            }
            if (pair == 0) {
                uint32_t b1h[4][2], b1l[4][2];
                ldsm4t(b1h[0][0], b1h[0][1], b1h[1][0], b1h[1][1], B1u + bkof);
                ldsm4t(b1h[2][0], b1h[2][1], b1h[3][0], b1h[3][1], B1u + bkof + 32);
                ldsm4t(b1l[0][0], b1l[0][1], b1l[1][0], b1l[1][1], B1u + PV_BT * 2 + bkof);
                ldsm4t(b1l[2][0], b1l[2][1], b1l[3][0], b1l[3][1], B1u + PV_BT * 2 + bkof + 32);
                #pragma unroll
                for (int j = 0; j < 4; j++) mma16816(acc1[j], a1h, b1h[j]);
                #pragma unroll
                for (int j = 0; j < 4; j++) mma16816(acc1[j], a1h, b1l[j]);
                #pragma unroll
                for (int j = 0; j < 4; j++) mma16816(acc1[j], a1l, b1h[j]);
            } else {
                #pragma unroll
                for (int j = 0; j < 4; j++) mma16816(acc1[j], a1h, b0h[j]);
                #pragma unroll
                for (int j = 0; j < 4; j++) mma16816(acc1[j], a1h, b0l[j]);
                #pragma unroll
                for (int j = 0; j < 4; j++) mma16816(acc1[j], a1l, b0h[j]);
            }
        }
    }

    // ---- epilogue ----
    const int r0g = n0 + rowblk + g;
    #pragma unroll
    for (int j = 0; j < 4; j++) {
        int col = h * ND + (j << 3) + (tig << 1);
        uint32_t hi, lo;
        if (pair == 0) {
            size_t ro0 = (size_t)(b * NN + r0g) * NE + col;
            size_t ro1 = (size_t)(b * NN + r0g + 8) * NE + col;
            split2(acc0[j][0], acc0[j][1], hi, lo);
            *(uint32_t*)(outh + ro0) = hi; *(uint32_t*)(outl + ro0) = lo;
            split2(acc0[j][2], acc0[j][3], hi, lo);
            *(uint32_t*)(outh + ro1) = hi; *(uint32_t*)(outl + ro1) = lo;
            size_t vo0 = VOFF + ((size_t)(b * NN + r0g) * 3 + 0) * NE + col;
            size_t vo1 = VOFF + ((size_t)(b * NN + r0g + 8) * 3 + 0) * NE + col;
            split2(acc1[j][0], acc1[j][1], hi, lo);
            *(uint32_t*)(outh + vo0) = hi; *(uint32_t*)(outl + vo0) = lo;
            split2(acc1[j][2], acc1[j][3], hi, lo);
            *(uint32_t*)(outh + vo1) = hi; *(uint32_t*)(outl + vo1) = lo;
        } else {
            size_t vo0 = VOFF + ((size_t)(b * NN + r0g) * 3 + 1) * NE + col;
            size_t vo1 = VOFF + ((size_t)(b * NN + r0g + 8) * 3 + 1) * NE + col;
            split2(acc0[j][0], acc0[j][1], hi, lo);
            *(uint32_t*)(outh + vo0) = hi; *(uint32_t*)(outl + vo0) = lo;
            split2(acc0[j][2], acc0[j][3], hi, lo);
            *(uint32_t*)(outh + vo1) = hi; *(uint32_t*)(outl + vo1) = lo;
            size_t wo0 = VOFF + ((size_t)(b * NN + r0g) * 3 + 2) * NE + col;
            size_t wo1 = VOFF + ((size_t)(b * NN + r0g + 8) * 3 + 2) * NE + col;
            split2(acc1[j][0], acc1[j][1], hi, lo);
            *(uint32_t*)(outh + wo0) = hi; *(uint32_t*)(outl + wo0) = lo;
            split2(acc1[j][2], acc1[j][3], hi, lo);
            *(uint32_t*)(outh + wo1) = hi; *(uint32_t*)(outl + wo1) = lo;
        }
    }
}

// ============================================================================
// launch
// ============================================================================
extern "C" void kernel_launch(void* const* d_in, const int* in_sizes, int n_in,
                              void* d_out, int out_size)
{
    const float* x    = (const float*)d_in[0];
    const float* pos  = (const float*)d_in[1];
    const float* epos = (const float*)d_in[2];
    const float* bias = (const float*)d_in[3];
    const unsigned char* pmask = (const unsigned char*)d_in[4];
    const unsigned char* emask = (const unsigned char*)d_in[5];
    const int*   oidx = (const int*)d_in[6];
    const float* Wq   = (const float*)d_in[7];
    const float* Wk   = (const float*)d_in[8];
    const float* Wv   = (const float*)d_in[9];
    const float* Wve  = (const float*)d_in[10];
    const float* Wo   = (const float*)d_in[11];
    const float* Woe  = (const float*)d_in[12];
    float* out = (float*)d_out;

    __nv_bfloat16 *ah, *al, *wh, *wl, *ph, *pl;
    float *dlt, *att;
    cudaGetSymbolAddress((void**)&ah,  g_ah);
    cudaGetSymbolAddress((void**)&al,  g_al);
    cudaGetSymbolAddress((void**)&wh,  g_wh);
    cudaGetSymbolAddress((void**)&wl,  g_wl);
    cudaGetSymbolAddress((void**)&ph,  g_projh);
    cudaGetSymbolAddress((void**)&pl,  g_projl);
    cudaGetSymbolAddress((void**)&dlt, g_delta);
    cudaGetSymbolAddress((void**)&att, g_attn);

    cudaFuncSetAttribute(gemm_mma,   cudaFuncAttributeMaxDynamicSharedMemorySize, GSMEM_BYTES);
    cudaFuncSetAttribute(qk_softmax, cudaFuncAttributeMaxDynamicSharedMemorySize, QK_SMEM);
    cudaFuncSetAttribute(pv_mma,     cudaFuncAttributeMaxDynamicSharedMemorySize, PV_SMEM);

    const int WSZ = 1024 * 1024;

    // 1) merged prep
    prep<<<14336, 256>>>(x, Wq, Wk, Wv, Wve, Woe, Wo,
                         pos, epos, pmask, emask,
                         ah, al, wh, wl, dlt);

    // 2) projections -> bf16 hi/lo (mode 1)
    gemm_mma<<<dim3(8, 32, 4), 256, GSMEM_BYTES>>>(ah, al, wh, wl,
                                                   nullptr, nullptr, 1024,
                                                   nullptr, ph, pl, SCALING_F, 1);

    // 3) fused QK + softmax
    qk_softmax<<<dim3(8, 256), 256, QK_SMEM>>>(bias, oidx, pmask, emask,
                                               ph, pl, ph + PSZ, pl + PSZ);

    // 4) fused PV + vec (pipelined gather)
    pv_mma<<<dim3(4, 32, 8), 256, PV_SMEM>>>(att, dlt, oidx,
                                             ph + 2*PSZ, pl + 2*PSZ,
                                             ph + 3*PSZ, pl + 3*PSZ,
                                             ah, al);

    // 5) fused output GEMMs
    gemm_mma<<<dim3(8, 128, 1), 256, GSMEM_BYTES>>>(ah, al,
                                                    wh + 4*WSZ, wl + 4*WSZ,
                                                    wh + 5*WSZ, wl + 5*WSZ, 32,
                                                    out, nullptr, nullptr, 1.0f, 0);
}